// round 10
// baseline (speedup 1.0000x reference)
#include <cuda_runtime.h>
#include <cuda_bf16.h>
#include <math.h>
#include <stdint.h>

#define N_SEQ   4096
#define DMODEL  1024
#define HEADS   8
#define DH      64
#define DINNER  512
#define QKVC    1536
#define WIN     128
#define NPERSIST 4

// ---------------- scratch (device globals; allocation-free rule) ------------
__device__ float g_qkv[N_SEQ * QKVC];
__device__ __nv_bfloat16 g_a_hi[N_SEQ * DMODEL];
__device__ __nv_bfloat16 g_a_lo[N_SEQ * DMODEL];
__device__ __nv_bfloat16 g_wqkvT_hi[QKVC * DMODEL];
__device__ __nv_bfloat16 g_wqkvT_lo[QKVC * DMODEL];
__device__ __nv_bfloat16 g_woutT_hi[DMODEL * DINNER];
__device__ __nv_bfloat16 g_woutT_lo[DMODEL * DINNER];
__device__ __nv_bfloat16 g_attn_hi[N_SEQ * DINNER];
__device__ __nv_bfloat16 g_attn_lo[N_SEQ * DINNER];

// ---------------- helpers ----------------------------------------------
__device__ __forceinline__ uint32_t smem_u32(const void* p) {
    uint32_t a;
    asm("{ .reg .u64 t; cvta.to.shared.u64 t, %1; cvt.u32.u64 %0, t; }" : "=r"(a) : "l"(p));
    return a;
}
__device__ __forceinline__ void cp_async16(uint32_t dst, const void* src) {
    asm volatile("cp.async.cg.shared.global [%0], [%1], 16;" :: "r"(dst), "l"(src));
}
__device__ __forceinline__ void cp_commit() {
    asm volatile("cp.async.commit_group;" ::: "memory");
}
template <int N>
__device__ __forceinline__ void cp_wait() {
    asm volatile("cp.async.wait_group %0;" :: "n"(N) : "memory");
}
__device__ __forceinline__ void ldm_x4(uint32_t& r0, uint32_t& r1, uint32_t& r2,
                                       uint32_t& r3, uint32_t addr) {
    asm volatile("ldmatrix.sync.aligned.m8n8.x4.shared.b16 {%0,%1,%2,%3}, [%4];"
                 : "=r"(r0), "=r"(r1), "=r"(r2), "=r"(r3) : "r"(addr));
}
__device__ __forceinline__ void mma_bf16(float* d, const uint32_t* a, const uint32_t* b) {
    asm volatile("mma.sync.aligned.m16n8k16.row.col.f32.bf16.bf16.f32 "
                 "{%0,%1,%2,%3}, {%4,%5,%6,%7}, {%8,%9}, {%0,%1,%2,%3};"
                 : "+f"(d[0]), "+f"(d[1]), "+f"(d[2]), "+f"(d[3])
                 : "r"(a[0]), "r"(a[1]), "r"(a[2]), "r"(a[3]), "r"(b[0]), "r"(b[1]));
}

// ---------------------------------------------------------------------------
// RMSNorm -> bf16 hi/lo
// ---------------------------------------------------------------------------
__global__ void rmsnorm_cvt_kernel(const float* __restrict__ seq,
                                   const float* __restrict__ g,
                                   __nv_bfloat16* __restrict__ hi,
                                   __nv_bfloat16* __restrict__ lo) {
    int row = blockIdx.x;
    int t = threadIdx.x;
    float4 v = ((const float4*)(seq + row * DMODEL))[t];
    float ss = v.x * v.x + v.y * v.y + v.z * v.z + v.w * v.w;
#pragma unroll
    for (int o = 16; o > 0; o >>= 1) ss += __shfl_xor_sync(0xffffffffu, ss, o);
    __shared__ float ws[8];
    if ((t & 31) == 0) ws[t >> 5] = ss;
    __syncthreads();
    float tot = ws[0] + ws[1] + ws[2] + ws[3] + ws[4] + ws[5] + ws[6] + ws[7];
    float inv = rsqrtf(tot * (1.0f / (float)DMODEL) + 1.1920929e-07f);
    float4 gv = ((const float4*)g)[t];
    float x0 = v.x * inv * gv.x, x1 = v.y * inv * gv.y;
    float x2 = v.z * inv * gv.z, x3 = v.w * inv * gv.w;
    size_t base = (size_t)row * DMODEL + t * 4;
    __nv_bfloat16 h0 = __float2bfloat16(x0), h1 = __float2bfloat16(x1);
    __nv_bfloat16 h2 = __float2bfloat16(x2), h3 = __float2bfloat16(x3);
    __nv_bfloat162 hp0; hp0.x = h0; hp0.y = h1;
    __nv_bfloat162 hp1; hp1.x = h2; hp1.y = h3;
    *(__nv_bfloat162*)(hi + base) = hp0;
    *(__nv_bfloat162*)(hi + base + 2) = hp1;
    __nv_bfloat162 lp0, lp1;
    lp0.x = __float2bfloat16(x0 - __bfloat162float(h0));
    lp0.y = __float2bfloat16(x1 - __bfloat162float(h1));
    lp1.x = __float2bfloat16(x2 - __bfloat162float(h2));
    lp1.y = __float2bfloat16(x3 - __bfloat162float(h3));
    *(__nv_bfloat162*)(lo + base) = lp0;
    *(__nv_bfloat162*)(lo + base + 2) = lp1;
}

// ---------------------------------------------------------------------------
// Transpose + bf16 hi/lo split: src[K][N] -> dst[N][K]
// ---------------------------------------------------------------------------
__global__ void transpose_cvt_kernel(const float* __restrict__ src, int K, int N,
                                     __nv_bfloat16* __restrict__ hi,
                                     __nv_bfloat16* __restrict__ lo) {
    __shared__ float tile[32][33];
    int bx = blockIdx.x, by = blockIdx.y;
    int tx = threadIdx.x, ty = threadIdx.y;
#pragma unroll
    for (int i = 0; i < 4; i++) {
        int k = by * 32 + ty + 8 * i;
        int n = bx * 32 + tx;
        tile[ty + 8 * i][tx] = src[(size_t)k * N + n];
    }
    __syncthreads();
#pragma unroll
    for (int i = 0; i < 4; i++) {
        int n = bx * 32 + ty + 8 * i;
        int k = by * 32 + tx;
        float v = tile[tx][ty + 8 * i];
        __nv_bfloat16 h = __float2bfloat16(v);
        hi[(size_t)n * K + k] = h;
        lo[(size_t)n * K + k] = __float2bfloat16(v - __bfloat162float(h));
    }
}

// ---------------------------------------------------------------------------
// Split-bf16 GEMM via mma.sync (HMMA). Interleaved per-tile MMA ordering
// (measured fastest). Optional fused RoPE epilogue on columns < rope_cols.
// ---------------------------------------------------------------------------
#define GEMM_SMEM (2 * 4 * 16384)

struct Frag {
    uint32_t ah[4][4], al[4][4], bh[4][2], bl[4][2];
};

__global__ __launch_bounds__(256, 1)
void gemm_sb16_kernel(const __nv_bfloat16* __restrict__ Ahi,
                      const __nv_bfloat16* __restrict__ Alo,
                      const __nv_bfloat16* __restrict__ Bhi,
                      const __nv_bfloat16* __restrict__ Blo,
                      float* __restrict__ C, int K, int ldc, int rope_cols) {
    extern __shared__ char smem[];
    uint32_t sb = smem_u32(smem);
    int tid = threadIdx.x;
    int wid = tid >> 5, lane = tid & 31;
    int m0 = blockIdx.y * 128, n0 = blockIdx.x * 128;
    int wm = wid & 1;
    int wn = wid >> 1;

    auto prefetch = [&](int c, int buf) {
        int kc = c << 6;
        uint32_t b32 = sb + buf * 65536;
#pragma unroll
        for (int i = 0; i < 4; i++) {
            int idx = tid + 256 * i;
            int r = idx >> 3, u = idx & 7;
            uint32_t dst = b32 + r * 128 + ((u ^ (r & 7)) << 4);
            size_t ga = (size_t)(m0 + r) * K + kc + u * 8;
            size_t gb = (size_t)(n0 + r) * K + kc + u * 8;
            cp_async16(dst,         Ahi + ga);
            cp_async16(dst + 16384, Alo + ga);
            cp_async16(dst + 32768, Bhi + gb);
            cp_async16(dst + 49152, Blo + gb);
        }
        cp_commit();
    };

    auto load_frags = [&](uint32_t b32, int ks, Frag& f) {
#pragma unroll
        for (int mt = 0; mt < 4; mt++) {
            int r = wm * 64 + mt * 16 + (lane & 15);
            int u = 2 * ks + (lane >> 4);
            uint32_t addr = b32 + r * 128 + ((u ^ (r & 7)) << 4);
            ldm_x4(f.ah[mt][0], f.ah[mt][1], f.ah[mt][2], f.ah[mt][3], addr);
            ldm_x4(f.al[mt][0], f.al[mt][1], f.al[mt][2], f.al[mt][3], addr + 16384);
        }
#pragma unroll
        for (int np = 0; np < 2; np++) {
            int r = wn * 32 + np * 16 + (lane & 15);
            int u = 2 * ks + (lane >> 4);
            uint32_t addr = b32 + 32768 + r * 128 + ((u ^ (r & 7)) << 4);
            uint32_t t0, t1, t2, t3;
            ldm_x4(t0, t1, t2, t3, addr);
            f.bh[2 * np][0] = t0; f.bh[2 * np][1] = t2;
            f.bh[2 * np + 1][0] = t1; f.bh[2 * np + 1][1] = t3;
            ldm_x4(t0, t1, t2, t3, addr + 16384);   // Blo plane
            f.bl[2 * np][0] = t0; f.bl[2 * np][1] = t2;
            f.bl[2 * np + 1][0] = t1; f.bl[2 * np + 1][1] = t3;
        }
    };

    float acc[4][4][4];
#pragma unroll
    for (int i = 0; i < 4; i++)
#pragma unroll
        for (int j = 0; j < 4; j++)
#pragma unroll
            for (int k = 0; k < 4; k++) acc[i][j][k] = 0.f;

    int NC = K >> 6;
    prefetch(0, 0);

    Frag f0, f1;
    for (int c = 0; c < NC; c++) {
        int buf = c & 1;
        if (c + 1 < NC) {
            prefetch(c + 1, buf ^ 1);
            cp_wait<1>();
        } else {
            cp_wait<0>();
        }
        __syncthreads();

        uint32_t b32 = sb + buf * 65536;
        load_frags(b32, 0, f0);
#pragma unroll
        for (int ks = 0; ks < 4; ks++) {
            Frag& cur = (ks & 1) ? f1 : f0;
            Frag& nxt = (ks & 1) ? f0 : f1;
            if (ks < 3) load_frags(b32, ks + 1, nxt);
#pragma unroll
            for (int mt = 0; mt < 4; mt++)
#pragma unroll
                for (int nt = 0; nt < 4; nt++) {
                    mma_bf16(acc[mt][nt], cur.ah[mt], cur.bh[nt]);
                    mma_bf16(acc[mt][nt], cur.ah[mt], cur.bl[nt]);
                    mma_bf16(acc[mt][nt], cur.al[mt], cur.bh[nt]);
                }
        }
        __syncthreads();
    }

    int rbase = m0 + wm * 64 + (lane >> 2);
    int cbase = n0 + wn * 32 + (lane & 3) * 2;

    float invf[4];
    if (rope_cols > 0) {
#pragma unroll
        for (int nt = 0; nt < 4; nt++) {
            int t = ((cbase + nt * 8) & 63) >> 1;
            invf[nt] = (float)exp(-(double)t * (9.210340371976184 / 32.0));
        }
    }

#pragma unroll
    for (int mt = 0; mt < 4; mt++)
#pragma unroll
        for (int nt = 0; nt < 4; nt++) {
            int row = rbase + mt * 16;
            int col = cbase + nt * 8;
            float2 v0 = make_float2(acc[mt][nt][0], acc[mt][nt][1]);
            float2 v1 = make_float2(acc[mt][nt][2], acc[mt][nt][3]);
            if (col < rope_cols) {
                float s, cc;
                sincosf((float)row * invf[nt], &s, &cc);
                float a = v0.x, b = v0.y;
                v0.x = a * cc - b * s;
                v0.y = b * cc + a * s;
                sincosf((float)(row + 8) * invf[nt], &s, &cc);
                a = v1.x; b = v1.y;
                v1.x = a * cc - b * s;
                v1.y = b * cc + a * s;
            }
            *(float2*)(C + (size_t)row * ldc + col) = v0;
            *(float2*)(C + (size_t)(row + 8) * ldc + col) = v1;
        }
}

// ---------------------------------------------------------------------------
// Fused sliding-window attention v3: adjacent query pairs share K/V reads.
// 128 threads = 32 pairs x 4 lanes; each lane owns a 16-dim quarter of BOTH
// queries (qa = qs+2*pair, qb = qa+1). SMEM traffic halved vs v2.
// ---------------------------------------------------------------------------
#define MAX_KEYS 196
#define ATTN_SMEM (2 * MAX_KEYS * 64 * 4)
#define SW(r, u) ((u) ^ (((u) & 8) >> 1) ^ ((r) & 7))

__global__ __launch_bounds__(128) void attn_kernel(const float* __restrict__ qkv,
                                                   __nv_bfloat16* __restrict__ out_hi,
                                                   __nv_bfloat16* __restrict__ out_lo) {
    extern __shared__ float smemf[];
    float4* Ks = (float4*)smemf;
    float4* Vs = (float4*)(smemf + MAX_KEYS * 64);

    int h = blockIdx.y;
    int qs = blockIdx.x * 64;
    int tid = threadIdx.x;

    int kv_lo = qs - WIN; if (kv_lo < 0) kv_lo = 0;
    int cnt = qs + 64 - kv_lo;
    int P = (kv_lo > 0) ? NPERSIST : 0;
    int tot = cnt + P;

    for (int idx = tid; idx < tot * 16; idx += 128) {
        int r = idx >> 4;
        int u = idx & 15;
        int gk = (r < cnt) ? (kv_lo + r) : (r - cnt);
        const float* base = qkv + (size_t)gk * QKVC + h * DH + u * 4;
        int su = r * 16 + SW(r, u);
        Ks[su] = *(const float4*)(base + DINNER);
        Vs[su] = *(const float4*)(base + 2 * DINNER);
    }
    __syncthreads();

    int pairId = tid >> 2;
    int sub = tid & 3;
    int qa = qs + 2 * pairId;
    int qb = qa + 1;
    int lane = tid & 31;
    unsigned gmask = 0xFu << (lane & 28);
    int ubase = sub * 4;               // first 16B unit of this thread's quarter

    float qav[16], qbv[16], oa[16], ob[16];
    {
        const float4* pa = (const float4*)(qkv + (size_t)qa * QKVC + h * DH + sub * 16);
        const float4* pb = (const float4*)(qkv + (size_t)qb * QKVC + h * DH + sub * 16);
#pragma unroll
        for (int i = 0; i < 4; i++) {
            float4 va = pa[i], vb = pb[i];
            qav[4 * i] = va.x; qav[4 * i + 1] = va.y; qav[4 * i + 2] = va.z; qav[4 * i + 3] = va.w;
            qbv[4 * i] = vb.x; qbv[4 * i + 1] = vb.y; qbv[4 * i + 2] = vb.z; qbv[4 * i + 3] = vb.w;
            oa[4 * i] = 0.f; oa[4 * i + 1] = 0.f; oa[4 * i + 2] = 0.f; oa[4 * i + 3] = 0.f;
            ob[4 * i] = 0.f; ob[4 * i + 1] = 0.f; ob[4 * i + 2] = 0.f; ob[4 * i + 3] = 0.f;
        }
    }

    float ma = -INFINITY, la = 0.f, mb = -INFINITY, lb = 0.f;

    auto chunk2 = [&](int r0, int r1, bool va0, bool vb0, bool va1, bool vb1) {
        float sa0 = 0.f, sb0 = 0.f, sa1 = 0.f, sb1 = 0.f;
#pragma unroll
        for (int i = 0; i < 4; i++) {
            float4 k0 = Ks[r0 * 16 + SW(r0, ubase + i)];
            float4 k1 = Ks[r1 * 16 + SW(r1, ubase + i)];
            float a0 = qav[4 * i], a1 = qav[4 * i + 1], a2 = qav[4 * i + 2], a3 = qav[4 * i + 3];
            float b0 = qbv[4 * i], b1 = qbv[4 * i + 1], b2 = qbv[4 * i + 2], b3 = qbv[4 * i + 3];
            sa0 = fmaf(a0, k0.x, sa0); sa0 = fmaf(a1, k0.y, sa0);
            sa0 = fmaf(a2, k0.z, sa0); sa0 = fmaf(a3, k0.w, sa0);
            sb0 = fmaf(b0, k0.x, sb0); sb0 = fmaf(b1, k0.y, sb0);
            sb0 = fmaf(b2, k0.z, sb0); sb0 = fmaf(b3, k0.w, sb0);
            sa1 = fmaf(a0, k1.x, sa1); sa1 = fmaf(a1, k1.y, sa1);
            sa1 = fmaf(a2, k1.z, sa1); sa1 = fmaf(a3, k1.w, sa1);
            sb1 = fmaf(b0, k1.x, sb1); sb1 = fmaf(b1, k1.y, sb1);
            sb1 = fmaf(b2, k1.z, sb1); sb1 = fmaf(b3, k1.w, sb1);
        }
        sa0 += __shfl_xor_sync(gmask, sa0, 1); sa0 += __shfl_xor_sync(gmask, sa0, 2);
        sb0 += __shfl_xor_sync(gmask, sb0, 1); sb0 += __shfl_xor_sync(gmask, sb0, 2);
        sa1 += __shfl_xor_sync(gmask, sa1, 1); sa1 += __shfl_xor_sync(gmask, sa1, 2);
        sb1 += __shfl_xor_sync(gmask, sb1, 1); sb1 += __shfl_xor_sync(gmask, sb1, 2);
        sa0 *= 0.125f; sb0 *= 0.125f; sa1 *= 0.125f; sb1 *= 0.125f;
        if (!va0) sa0 = -INFINITY;
        if (!vb0) sb0 = -INFINITY;
        if (!va1) sa1 = -INFINITY;
        if (!vb1) sb1 = -INFINITY;

        float mna = fmaxf(ma, fmaxf(sa0, sa1));
        float ca, pa0, pa1;
        if (mna == -INFINITY) { ca = 1.f; pa0 = 0.f; pa1 = 0.f; }
        else {
            ca = __expf(ma - mna);
            pa0 = __expf(sa0 - mna);
            pa1 = __expf(sa1 - mna);
            ma = mna;
        }
        la = la * ca + (pa0 + pa1);

        float mnb = fmaxf(mb, fmaxf(sb0, sb1));
        float cb, pb0, pb1;
        if (mnb == -INFINITY) { cb = 1.f; pb0 = 0.f; pb1 = 0.f; }
        else {
            cb = __expf(mb - mnb);
            pb0 = __expf(sb0 - mnb);
            pb1 = __expf(sb1 - mnb);
            mb = mnb;
        }
        lb = lb * cb + (pb0 + pb1);

#pragma unroll
        for (int i = 0; i < 4; i++) {
            float4 v0 = Vs[r0 * 16 + SW(r0, ubase + i)];
            float4 v1 = Vs[r1 * 16 + SW(r1, ubase + i)];
            float t;
            t = oa[4 * i] * ca;     t = fmaf(pa0, v0.x, t); oa[4 * i]     = fmaf(pa1, v1.x, t);
            t = oa[4 * i + 1] * ca; t = fmaf(pa0, v0.y, t); oa[4 * i + 1] = fmaf(pa1, v1.y, t);
            t = oa[4 * i + 2] * ca; t = fmaf(pa0, v0.z, t); oa[4 * i + 2] = fmaf(pa1, v1.z, t);
            t = oa[4 * i + 3] * ca; t = fmaf(pa0, v0.w, t); oa[4 * i + 3] = fmaf(pa1, v1.w, t);
            t = ob[4 * i] * cb;     t = fmaf(pb0, v0.x, t); ob[4 * i]     = fmaf(pb1, v1.x, t);
            t = ob[4 * i + 1] * cb; t = fmaf(pb0, v0.y, t); ob[4 * i + 1] = fmaf(pb1, v1.y, t);
            t = ob[4 * i + 2] * cb; t = fmaf(pb0, v0.z, t); ob[4 * i + 2] = fmaf(pb1, v1.z, t);
            t = ob[4 * i + 3] * cb; t = fmaf(pb0, v0.w, t); ob[4 * i + 3] = fmaf(pb1, v1.w, t);
        }
    };

    // persist coverage thresholds: keys < cov are NOT in the main loop
    int cova = qa - WIN; if (cova < 0) cova = 0;
    int covb = qb - WIN; if (covb < 0) covb = 0;

    if (covb > 0) {
        int base = (kv_lo > 0) ? cnt : 0;
        chunk2(base + 0, base + 1, 0 < cova, 0 < covb, 1 < cova, 1 < covb);
        chunk2(base + 2, base + 3, 2 < cova, 2 < covb, 3 < cova, 3 < covb);
    }

    // main loop: rows [jlo .. jhi], even count by construction
    int jlo = qa - WIN - kv_lo; if (jlo < 0) jlo = 0;
    int jhi = qb - kv_lo;
    for (int j = jlo; j < jhi; j += 2) {
        int jg = kv_lo + j;
        // key j:   va = (jg <= qa), vb = (jg >= qb - WIN)
        // key j+1: va = (jg+1 <= qa), vb = (jg+1 >= qb - WIN)
        chunk2(j, j + 1,
               jg <= qa, jg >= qb - WIN,
               jg + 1 <= qa, jg + 1 >= qb - WIN);
    }

    float invla = 1.0f / la;
    float invlb = 1.0f / lb;
    size_t oba = (size_t)qa * DINNER + h * DH + sub * 16;
    size_t obb = (size_t)qb * DINNER + h * DH + sub * 16;
#pragma unroll
    for (int i = 0; i < 4; i++) {
        float a0 = oa[4 * i] * invla, a1 = oa[4 * i + 1] * invla;
        float a2 = oa[4 * i + 2] * invla, a3 = oa[4 * i + 3] * invla;
        float b0 = ob[4 * i] * invlb, b1 = ob[4 * i + 1] * invlb;
        float b2 = ob[4 * i + 2] * invlb, b3 = ob[4 * i + 3] * invlb;

        __nv_bfloat16 ha0 = __float2bfloat16(a0), ha1 = __float2bfloat16(a1);
        __nv_bfloat16 ha2 = __float2bfloat16(a2), ha3 = __float2bfloat16(a3);
        __nv_bfloat162 w;
        w.x = ha0; w.y = ha1; *(__nv_bfloat162*)(out_hi + oba + 4 * i) = w;
        w.x = ha2; w.y = ha3; *(__nv_bfloat162*)(out_hi + oba + 4 * i + 2) = w;
        w.x = __float2bfloat16(a0 - __bfloat162float(ha0));
        w.y = __float2bfloat16(a1 - __bfloat162float(ha1));
        *(__nv_bfloat162*)(out_lo + oba + 4 * i) = w;
        w.x = __float2bfloat16(a2 - __bfloat162float(ha2));
        w.y = __float2bfloat16(a3 - __bfloat162float(ha3));
        *(__nv_bfloat162*)(out_lo + oba + 4 * i + 2) = w;

        __nv_bfloat16 hb0 = __float2bfloat16(b0), hb1 = __float2bfloat16(b1);
        __nv_bfloat16 hb2 = __float2bfloat16(b2), hb3 = __float2bfloat16(b3);
        w.x = hb0; w.y = hb1; *(__nv_bfloat162*)(out_hi + obb + 4 * i) = w;
        w.x = hb2; w.y = hb3; *(__nv_bfloat162*)(out_hi + obb + 4 * i + 2) = w;
        w.x = __float2bfloat16(b0 - __bfloat162float(hb0));
        w.y = __float2bfloat16(b1 - __bfloat162float(hb1));
        *(__nv_bfloat162*)(out_lo + obb + 4 * i) = w;
        w.x = __float2bfloat16(b2 - __bfloat162float(hb2));
        w.y = __float2bfloat16(b3 - __bfloat162float(hb3));
        *(__nv_bfloat162*)(out_lo + obb + 4 * i + 2) = w;
    }
}

// ---------------------------------------------------------------------------
extern "C" void kernel_launch(void* const* d_in, const int* in_sizes, int n_in,
                              void* d_out, int out_size) {
    const float* seq   = (const float*)d_in[0];
    const float* g     = (const float*)d_in[1];
    const float* w_qkv = (const float*)d_in[2];
    const float* w_out = (const float*)d_in[3];
    float* out = (float*)d_out;

    float* qkvp;
    __nv_bfloat16 *ahi, *alo, *wqh, *wql, *woh, *wol, *athi, *atlo;
    cudaGetSymbolAddress((void**)&qkvp, g_qkv);
    cudaGetSymbolAddress((void**)&ahi, g_a_hi);
    cudaGetSymbolAddress((void**)&alo, g_a_lo);
    cudaGetSymbolAddress((void**)&wqh, g_wqkvT_hi);
    cudaGetSymbolAddress((void**)&wql, g_wqkvT_lo);
    cudaGetSymbolAddress((void**)&woh, g_woutT_hi);
    cudaGetSymbolAddress((void**)&wol, g_woutT_lo);
    cudaGetSymbolAddress((void**)&athi, g_attn_hi);
    cudaGetSymbolAddress((void**)&atlo, g_attn_lo);

    cudaFuncSetAttribute(attn_kernel, cudaFuncAttributeMaxDynamicSharedMemorySize,
                         ATTN_SMEM);
    cudaFuncSetAttribute(gemm_sb16_kernel, cudaFuncAttributeMaxDynamicSharedMemorySize,
                         GEMM_SMEM);

    rmsnorm_cvt_kernel<<<N_SEQ, 256>>>(seq, g, ahi, alo);
    transpose_cvt_kernel<<<dim3(QKVC / 32, DMODEL / 32), dim3(32, 8)>>>(
        w_qkv, DMODEL, QKVC, wqh, wql);
    transpose_cvt_kernel<<<dim3(DMODEL / 32, DINNER / 32), dim3(32, 8)>>>(
        w_out, DINNER, DMODEL, woh, wol);

    // QKV GEMM with fused RoPE on q,k columns (< 1024)
    gemm_sb16_kernel<<<dim3(QKVC / 128, N_SEQ / 128), 256, GEMM_SMEM>>>(
        ahi, alo, wqh, wql, qkvp, DMODEL, QKVC, 2 * DINNER);

    attn_kernel<<<dim3(N_SEQ / 64, HEADS), 128, ATTN_SMEM>>>(qkvp, athi, atlo);

    gemm_sb16_kernel<<<dim3(DMODEL / 128, N_SEQ / 128), 256, GEMM_SMEM>>>(
        athi, atlo, woh, wol, out, DINNER, DMODEL, 0);
}

// round 11
// speedup vs baseline: 1.0393x; 1.0393x over previous
#include <cuda_runtime.h>
#include <cuda_bf16.h>
#include <math.h>
#include <stdint.h>

#define N_SEQ   4096
#define DMODEL  1024
#define HEADS   8
#define DH      64
#define DINNER  512
#define QKVC    1536
#define WIN     128
#define NPERSIST 4

// ---------------- scratch (device globals; allocation-free rule) ------------
__device__ float g_qkv[N_SEQ * QKVC];
__device__ float2 g_rope[N_SEQ * 32];                // (cos,sin) per (pos, pair)
__device__ __nv_bfloat16 g_a_hi[N_SEQ * DMODEL];
__device__ __nv_bfloat16 g_a_lo[N_SEQ * DMODEL];
__device__ __nv_bfloat16 g_wqkvT_hi[QKVC * DMODEL];
__device__ __nv_bfloat16 g_wqkvT_lo[QKVC * DMODEL];
__device__ __nv_bfloat16 g_woutT_hi[DMODEL * DINNER];
__device__ __nv_bfloat16 g_woutT_lo[DMODEL * DINNER];
__device__ __nv_bfloat16 g_attn_hi[N_SEQ * DINNER];
__device__ __nv_bfloat16 g_attn_lo[N_SEQ * DINNER];

// ---------------- helpers ----------------------------------------------
__device__ __forceinline__ uint32_t smem_u32(const void* p) {
    uint32_t a;
    asm("{ .reg .u64 t; cvta.to.shared.u64 t, %1; cvt.u32.u64 %0, t; }" : "=r"(a) : "l"(p));
    return a;
}
__device__ __forceinline__ void cp_async16(uint32_t dst, const void* src) {
    asm volatile("cp.async.cg.shared.global [%0], [%1], 16;" :: "r"(dst), "l"(src));
}
__device__ __forceinline__ void cp_commit() {
    asm volatile("cp.async.commit_group;" ::: "memory");
}
template <int N>
__device__ __forceinline__ void cp_wait() {
    asm volatile("cp.async.wait_group %0;" :: "n"(N) : "memory");
}
__device__ __forceinline__ void ldm_x4(uint32_t& r0, uint32_t& r1, uint32_t& r2,
                                       uint32_t& r3, uint32_t addr) {
    asm volatile("ldmatrix.sync.aligned.m8n8.x4.shared.b16 {%0,%1,%2,%3}, [%4];"
                 : "=r"(r0), "=r"(r1), "=r"(r2), "=r"(r3) : "r"(addr));
}
__device__ __forceinline__ void mma_bf16(float* d, const uint32_t* a, const uint32_t* b) {
    asm volatile("mma.sync.aligned.m16n8k16.row.col.f32.bf16.bf16.f32 "
                 "{%0,%1,%2,%3}, {%4,%5,%6,%7}, {%8,%9}, {%0,%1,%2,%3};"
                 : "+f"(d[0]), "+f"(d[1]), "+f"(d[2]), "+f"(d[3])
                 : "r"(a[0]), "r"(a[1]), "r"(a[2]), "r"(a[3]), "r"(b[0]), "r"(b[1]));
}

// ---------------------------------------------------------------------------
// RoPE table: g_rope[n*32+t] = (cos, sin)(n * 10000^(-t/32)). 131K sincosf.
// ---------------------------------------------------------------------------
__global__ void rope_table_kernel() {
    int idx = blockIdx.x * blockDim.x + threadIdx.x;
    if (idx >= N_SEQ * 32) return;
    int n = idx >> 5;
    int t = idx & 31;
    float inv = (float)exp(-(double)t * (9.210340371976184 / 32.0));
    float ang = (float)n * inv;
    float s, c;
    sincosf(ang, &s, &c);
    g_rope[idx] = make_float2(c, s);
}

// ---------------------------------------------------------------------------
// RMSNorm -> bf16 hi/lo
// ---------------------------------------------------------------------------
__global__ void rmsnorm_cvt_kernel(const float* __restrict__ seq,
                                   const float* __restrict__ g,
                                   __nv_bfloat16* __restrict__ hi,
                                   __nv_bfloat16* __restrict__ lo) {
    int row = blockIdx.x;
    int t = threadIdx.x;
    float4 v = ((const float4*)(seq + row * DMODEL))[t];
    float ss = v.x * v.x + v.y * v.y + v.z * v.z + v.w * v.w;
#pragma unroll
    for (int o = 16; o > 0; o >>= 1) ss += __shfl_xor_sync(0xffffffffu, ss, o);
    __shared__ float ws[8];
    if ((t & 31) == 0) ws[t >> 5] = ss;
    __syncthreads();
    float tot = ws[0] + ws[1] + ws[2] + ws[3] + ws[4] + ws[5] + ws[6] + ws[7];
    float inv = rsqrtf(tot * (1.0f / (float)DMODEL) + 1.1920929e-07f);
    float4 gv = ((const float4*)g)[t];
    float x0 = v.x * inv * gv.x, x1 = v.y * inv * gv.y;
    float x2 = v.z * inv * gv.z, x3 = v.w * inv * gv.w;
    size_t base = (size_t)row * DMODEL + t * 4;
    __nv_bfloat16 h0 = __float2bfloat16(x0), h1 = __float2bfloat16(x1);
    __nv_bfloat16 h2 = __float2bfloat16(x2), h3 = __float2bfloat16(x3);
    __nv_bfloat162 hp0; hp0.x = h0; hp0.y = h1;
    __nv_bfloat162 hp1; hp1.x = h2; hp1.y = h3;
    *(__nv_bfloat162*)(hi + base) = hp0;
    *(__nv_bfloat162*)(hi + base + 2) = hp1;
    __nv_bfloat162 lp0, lp1;
    lp0.x = __float2bfloat16(x0 - __bfloat162float(h0));
    lp0.y = __float2bfloat16(x1 - __bfloat162float(h1));
    lp1.x = __float2bfloat16(x2 - __bfloat162float(h2));
    lp1.y = __float2bfloat16(x3 - __bfloat162float(h3));
    *(__nv_bfloat162*)(lo + base) = lp0;
    *(__nv_bfloat162*)(lo + base + 2) = lp1;
}

// ---------------------------------------------------------------------------
// Transpose + bf16 hi/lo split: src[K][N] -> dst[N][K]
// ---------------------------------------------------------------------------
__global__ void transpose_cvt_kernel(const float* __restrict__ src, int K, int N,
                                     __nv_bfloat16* __restrict__ hi,
                                     __nv_bfloat16* __restrict__ lo) {
    __shared__ float tile[32][33];
    int bx = blockIdx.x, by = blockIdx.y;
    int tx = threadIdx.x, ty = threadIdx.y;
#pragma unroll
    for (int i = 0; i < 4; i++) {
        int k = by * 32 + ty + 8 * i;
        int n = bx * 32 + tx;
        tile[ty + 8 * i][tx] = src[(size_t)k * N + n];
    }
    __syncthreads();
#pragma unroll
    for (int i = 0; i < 4; i++) {
        int n = bx * 32 + ty + 8 * i;
        int k = by * 32 + tx;
        float v = tile[tx][ty + 8 * i];
        __nv_bfloat16 h = __float2bfloat16(v);
        hi[(size_t)n * K + k] = h;
        lo[(size_t)n * K + k] = __float2bfloat16(v - __bfloat162float(h));
    }
}

// ---------------------------------------------------------------------------
// Split-bf16 GEMM via mma.sync (HMMA), fused table-based RoPE epilogue on
// columns < rope_cols.
// ---------------------------------------------------------------------------
#define GEMM_SMEM (2 * 4 * 16384)

struct Frag {
    uint32_t ah[4][4], al[4][4], bh[4][2], bl[4][2];
};

__global__ __launch_bounds__(256, 1)
void gemm_sb16_kernel(const __nv_bfloat16* __restrict__ Ahi,
                      const __nv_bfloat16* __restrict__ Alo,
                      const __nv_bfloat16* __restrict__ Bhi,
                      const __nv_bfloat16* __restrict__ Blo,
                      float* __restrict__ C, int K, int ldc, int rope_cols) {
    extern __shared__ char smem[];
    uint32_t sb = smem_u32(smem);
    int tid = threadIdx.x;
    int wid = tid >> 5, lane = tid & 31;
    int m0 = blockIdx.y * 128, n0 = blockIdx.x * 128;
    int wm = wid & 1;
    int wn = wid >> 1;

    auto prefetch = [&](int c, int buf) {
        int kc = c << 6;
        uint32_t b32 = sb + buf * 65536;
#pragma unroll
        for (int i = 0; i < 4; i++) {
            int idx = tid + 256 * i;
            int r = idx >> 3, u = idx & 7;
            uint32_t dst = b32 + r * 128 + ((u ^ (r & 7)) << 4);
            size_t ga = (size_t)(m0 + r) * K + kc + u * 8;
            size_t gb = (size_t)(n0 + r) * K + kc + u * 8;
            cp_async16(dst,         Ahi + ga);
            cp_async16(dst + 16384, Alo + ga);
            cp_async16(dst + 32768, Bhi + gb);
            cp_async16(dst + 49152, Blo + gb);
        }
        cp_commit();
    };

    auto load_frags = [&](uint32_t b32, int ks, Frag& f) {
#pragma unroll
        for (int mt = 0; mt < 4; mt++) {
            int r = wm * 64 + mt * 16 + (lane & 15);
            int u = 2 * ks + (lane >> 4);
            uint32_t addr = b32 + r * 128 + ((u ^ (r & 7)) << 4);
            ldm_x4(f.ah[mt][0], f.ah[mt][1], f.ah[mt][2], f.ah[mt][3], addr);
            ldm_x4(f.al[mt][0], f.al[mt][1], f.al[mt][2], f.al[mt][3], addr + 16384);
        }
#pragma unroll
        for (int np = 0; np < 2; np++) {
            int r = wn * 32 + np * 16 + (lane & 15);
            int u = 2 * ks + (lane >> 4);
            uint32_t addr = b32 + 32768 + r * 128 + ((u ^ (r & 7)) << 4);
            uint32_t t0, t1, t2, t3;
            ldm_x4(t0, t1, t2, t3, addr);
            f.bh[2 * np][0] = t0; f.bh[2 * np][1] = t2;
            f.bh[2 * np + 1][0] = t1; f.bh[2 * np + 1][1] = t3;
            ldm_x4(t0, t1, t2, t3, addr + 16384);   // Blo plane
            f.bl[2 * np][0] = t0; f.bl[2 * np][1] = t2;
            f.bl[2 * np + 1][0] = t1; f.bl[2 * np + 1][1] = t3;
        }
    };

    float acc[4][4][4];
#pragma unroll
    for (int i = 0; i < 4; i++)
#pragma unroll
        for (int j = 0; j < 4; j++)
#pragma unroll
            for (int k = 0; k < 4; k++) acc[i][j][k] = 0.f;

    int NC = K >> 6;
    prefetch(0, 0);

    Frag f0, f1;
    for (int c = 0; c < NC; c++) {
        int buf = c & 1;
        if (c + 1 < NC) {
            prefetch(c + 1, buf ^ 1);
            cp_wait<1>();
        } else {
            cp_wait<0>();
        }
        __syncthreads();

        uint32_t b32 = sb + buf * 65536;
        load_frags(b32, 0, f0);
#pragma unroll
        for (int ks = 0; ks < 4; ks++) {
            Frag& cur = (ks & 1) ? f1 : f0;
            Frag& nxt = (ks & 1) ? f0 : f1;
            if (ks < 3) load_frags(b32, ks + 1, nxt);
#pragma unroll
            for (int mt = 0; mt < 4; mt++)
#pragma unroll
                for (int nt = 0; nt < 4; nt++) {
                    mma_bf16(acc[mt][nt], cur.ah[mt], cur.bh[nt]);
                    mma_bf16(acc[mt][nt], cur.ah[mt], cur.bl[nt]);
                    mma_bf16(acc[mt][nt], cur.al[mt], cur.bh[nt]);
                }
        }
        __syncthreads();
    }

    int rbase = m0 + wm * 64 + (lane >> 2);
    int cbase = n0 + wn * 32 + (lane & 3) * 2;

    int tt[4];
#pragma unroll
    for (int nt = 0; nt < 4; nt++) tt[nt] = ((cbase + nt * 8) & 63) >> 1;

#pragma unroll
    for (int mt = 0; mt < 4; mt++)
#pragma unroll
        for (int nt = 0; nt < 4; nt++) {
            int row = rbase + mt * 16;
            int col = cbase + nt * 8;
            float2 v0 = make_float2(acc[mt][nt][0], acc[mt][nt][1]);
            float2 v1 = make_float2(acc[mt][nt][2], acc[mt][nt][3]);
            if (col < rope_cols) {
                float2 cs0 = g_rope[row * 32 + tt[nt]];
                float2 cs1 = g_rope[(row + 8) * 32 + tt[nt]];
                float a = v0.x, b = v0.y;
                v0.x = a * cs0.x - b * cs0.y;
                v0.y = b * cs0.x + a * cs0.y;
                a = v1.x; b = v1.y;
                v1.x = a * cs1.x - b * cs1.y;
                v1.y = b * cs1.x + a * cs1.y;
            }
            *(float2*)(C + (size_t)row * ldc + col) = v0;
            *(float2*)(C + (size_t)(row + 8) * ldc + col) = v1;
        }
}

// ---------------------------------------------------------------------------
// Fused sliding-window attention (v2 chunk4, fastest measured) -> bf16 hi/lo.
// ---------------------------------------------------------------------------
#define MAX_KEYS 196
#define ATTN_SMEM (2 * MAX_KEYS * 64 * 4)
#define SW(r, u) ((u) ^ (((u) & 8) >> 1) ^ ((r) & 7))

__global__ __launch_bounds__(128) void attn_kernel(const float* __restrict__ qkv,
                                                   __nv_bfloat16* __restrict__ out_hi,
                                                   __nv_bfloat16* __restrict__ out_lo) {
    extern __shared__ float smemf[];
    float4* Ks = (float4*)smemf;
    float4* Vs = (float4*)(smemf + MAX_KEYS * 64);

    int h = blockIdx.y;
    int qs = blockIdx.x * 64;
    int tid = threadIdx.x;

    int kv_lo = qs - WIN; if (kv_lo < 0) kv_lo = 0;
    int cnt = qs + 64 - kv_lo;
    int P = (kv_lo > 0) ? NPERSIST : 0;
    int tot = cnt + P;

    for (int idx = tid; idx < tot * 16; idx += 128) {
        int r = idx >> 4;
        int u = idx & 15;
        int gk = (r < cnt) ? (kv_lo + r) : (r - cnt);
        const float* base = qkv + (size_t)gk * QKVC + h * DH + u * 4;
        int su = r * 16 + SW(r, u);
        Ks[su] = *(const float4*)(base + DINNER);
        Vs[su] = *(const float4*)(base + 2 * DINNER);
    }
    __syncthreads();

    int lq = tid >> 1;
    int half = tid & 1;
    int qidx = qs + lq;
    int lane = tid & 31;
    unsigned pairmask = 0x3u << (lane & 30);
    int ub = half * 8;

    float q[32], o[32];
    const float4* q4 = (const float4*)(qkv + (size_t)qidx * QKVC + h * DH + half * 32);
#pragma unroll
    for (int i = 0; i < 8; i++) {
        float4 v = q4[i];
        q[4 * i] = v.x; q[4 * i + 1] = v.y; q[4 * i + 2] = v.z; q[4 * i + 3] = v.w;
        o[4 * i] = 0.f; o[4 * i + 1] = 0.f; o[4 * i + 2] = 0.f; o[4 * i + 3] = 0.f;
    }

    float m = -INFINITY, l = 0.f;

    auto chunk4 = [&](int r0, int r1, int r2, int r3,
                      bool v1ok, bool v2ok, bool v3ok) {
        float a0 = 0.f, b0 = 0.f, a1 = 0.f, b1 = 0.f;
        float a2 = 0.f, b2 = 0.f, a3 = 0.f, b3 = 0.f;
#pragma unroll
        for (int i = 0; i < 8; i++) {
            float4 x0 = Ks[r0 * 16 + SW(r0, ub + i)];
            float4 x1 = Ks[r1 * 16 + SW(r1, ub + i)];
            float4 x2 = Ks[r2 * 16 + SW(r2, ub + i)];
            float4 x3 = Ks[r3 * 16 + SW(r3, ub + i)];
            float q0 = q[4 * i], q1 = q[4 * i + 1], q2 = q[4 * i + 2], q3 = q[4 * i + 3];
            if (i & 1) {
                b0 = fmaf(q0, x0.x, b0); b0 = fmaf(q1, x0.y, b0);
                b0 = fmaf(q2, x0.z, b0); b0 = fmaf(q3, x0.w, b0);
                b1 = fmaf(q0, x1.x, b1); b1 = fmaf(q1, x1.y, b1);
                b1 = fmaf(q2, x1.z, b1); b1 = fmaf(q3, x1.w, b1);
                b2 = fmaf(q0, x2.x, b2); b2 = fmaf(q1, x2.y, b2);
                b2 = fmaf(q2, x2.z, b2); b2 = fmaf(q3, x2.w, b2);
                b3 = fmaf(q0, x3.x, b3); b3 = fmaf(q1, x3.y, b3);
                b3 = fmaf(q2, x3.z, b3); b3 = fmaf(q3, x3.w, b3);
            } else {
                a0 = fmaf(q0, x0.x, a0); a0 = fmaf(q1, x0.y, a0);
                a0 = fmaf(q2, x0.z, a0); a0 = fmaf(q3, x0.w, a0);
                a1 = fmaf(q0, x1.x, a1); a1 = fmaf(q1, x1.y, a1);
                a1 = fmaf(q2, x1.z, a1); a1 = fmaf(q3, x1.w, a1);
                a2 = fmaf(q0, x2.x, a2); a2 = fmaf(q1, x2.y, a2);
                a2 = fmaf(q2, x2.z, a2); a2 = fmaf(q3, x2.w, a2);
                a3 = fmaf(q0, x3.x, a3); a3 = fmaf(q1, x3.y, a3);
                a3 = fmaf(q2, x3.z, a3); a3 = fmaf(q3, x3.w, a3);
            }
        }
        float s0 = a0 + b0, s1 = a1 + b1, s2 = a2 + b2, s3 = a3 + b3;
        s0 += __shfl_xor_sync(pairmask, s0, 1);
        s1 += __shfl_xor_sync(pairmask, s1, 1);
        s2 += __shfl_xor_sync(pairmask, s2, 1);
        s3 += __shfl_xor_sync(pairmask, s3, 1);
        s0 *= 0.125f; s1 *= 0.125f; s2 *= 0.125f; s3 *= 0.125f;
        if (!v1ok) s1 = -INFINITY;
        if (!v2ok) s2 = -INFINITY;
        if (!v3ok) s3 = -INFINITY;

        float mn = fmaxf(m, fmaxf(fmaxf(s0, s1), fmaxf(s2, s3)));
        float corr = __expf(m - mn);
        float p0 = __expf(s0 - mn);
        float p1 = __expf(s1 - mn);
        float p2 = __expf(s2 - mn);
        float p3 = __expf(s3 - mn);
        l = l * corr + ((p0 + p1) + (p2 + p3));
        m = mn;

#pragma unroll
        for (int i = 0; i < 8; i++) {
            float4 y0 = Vs[r0 * 16 + SW(r0, ub + i)];
            float4 y1 = Vs[r1 * 16 + SW(r1, ub + i)];
            float4 y2 = Vs[r2 * 16 + SW(r2, ub + i)];
            float4 y3 = Vs[r3 * 16 + SW(r3, ub + i)];
            float t0 = o[4 * i] * corr;
            float t1 = o[4 * i + 1] * corr;
            float t2 = o[4 * i + 2] * corr;
            float t3 = o[4 * i + 3] * corr;
            t0 = fmaf(p0, y0.x, t0); t1 = fmaf(p0, y0.y, t1);
            t2 = fmaf(p0, y0.z, t2); t3 = fmaf(p0, y0.w, t3);
            t0 = fmaf(p1, y1.x, t0); t1 = fmaf(p1, y1.y, t1);
            t2 = fmaf(p1, y1.z, t2); t3 = fmaf(p1, y1.w, t3);
            t0 = fmaf(p2, y2.x, t0); t1 = fmaf(p2, y2.y, t1);
            t2 = fmaf(p2, y2.z, t2); t3 = fmaf(p2, y2.w, t3);
            t0 = fmaf(p3, y3.x, t0); t1 = fmaf(p3, y3.y, t1);
            t2 = fmaf(p3, y3.z, t2); t3 = fmaf(p3, y3.w, t3);
            o[4 * i] = t0; o[4 * i + 1] = t1; o[4 * i + 2] = t2; o[4 * i + 3] = t3;
        }
    };

    int jlo = qidx - WIN - kv_lo; if (jlo < 0) jlo = 0;
    int jhi = qidx - kv_lo;
    int covered_lo = kv_lo + jlo;

    if (covered_lo > 0) {
        int base = (kv_lo > 0) ? cnt : 0;
        chunk4(base + 0, base + 1, base + 2, base + 3,
               1 < covered_lo && 1 < NPERSIST,
               2 < covered_lo && 2 < NPERSIST,
               3 < covered_lo && 3 < NPERSIST);
    }

    int j = jlo;
    for (; j + 3 <= jhi; j += 4) chunk4(j, j + 1, j + 2, j + 3, true, true, true);
    int rem = jhi - j + 1;
    if (rem > 0) {
        int r1 = (rem > 1) ? j + 1 : j;
        int r2 = (rem > 2) ? j + 2 : j;
        chunk4(j, r1, r2, j, rem > 1, rem > 2, false);
    }

    float invl = 1.0f / l;
    size_t obase = (size_t)qidx * DINNER + h * DH + half * 32;
#pragma unroll
    for (int i = 0; i < 8; i++) {
        float v0 = o[4 * i] * invl;
        float v1 = o[4 * i + 1] * invl;
        float v2 = o[4 * i + 2] * invl;
        float v3 = o[4 * i + 3] * invl;
        __nv_bfloat16 h0 = __float2bfloat16(v0), h1 = __float2bfloat16(v1);
        __nv_bfloat16 h2 = __float2bfloat16(v2), h3 = __float2bfloat16(v3);
        __nv_bfloat162 hp0; hp0.x = h0; hp0.y = h1;
        __nv_bfloat162 hp1; hp1.x = h2; hp1.y = h3;
        *(__nv_bfloat162*)(out_hi + obase + 4 * i) = hp0;
        *(__nv_bfloat162*)(out_hi + obase + 4 * i + 2) = hp1;
        __nv_bfloat162 lp0, lp1;
        lp0.x = __float2bfloat16(v0 - __bfloat162float(h0));
        lp0.y = __float2bfloat16(v1 - __bfloat162float(h1));
        lp1.x = __float2bfloat16(v2 - __bfloat162float(h2));
        lp1.y = __float2bfloat16(v3 - __bfloat162float(h3));
        *(__nv_bfloat162*)(out_lo + obase + 4 * i) = lp0;
        *(__nv_bfloat162*)(out_lo + obase + 4 * i + 2) = lp1;
    }
}

// ---------------------------------------------------------------------------
extern "C" void kernel_launch(void* const* d_in, const int* in_sizes, int n_in,
                              void* d_out, int out_size) {
    const float* seq   = (const float*)d_in[0];
    const float* g     = (const float*)d_in[1];
    const float* w_qkv = (const float*)d_in[2];
    const float* w_out = (const float*)d_in[3];
    float* out = (float*)d_out;

    float* qkvp;
    __nv_bfloat16 *ahi, *alo, *wqh, *wql, *woh, *wol, *athi, *atlo;
    cudaGetSymbolAddress((void**)&qkvp, g_qkv);
    cudaGetSymbolAddress((void**)&ahi, g_a_hi);
    cudaGetSymbolAddress((void**)&alo, g_a_lo);
    cudaGetSymbolAddress((void**)&wqh, g_wqkvT_hi);
    cudaGetSymbolAddress((void**)&wql, g_wqkvT_lo);
    cudaGetSymbolAddress((void**)&woh, g_woutT_hi);
    cudaGetSymbolAddress((void**)&wol, g_woutT_lo);
    cudaGetSymbolAddress((void**)&athi, g_attn_hi);
    cudaGetSymbolAddress((void**)&atlo, g_attn_lo);

    cudaFuncSetAttribute(attn_kernel, cudaFuncAttributeMaxDynamicSharedMemorySize,
                         ATTN_SMEM);
    cudaFuncSetAttribute(gemm_sb16_kernel, cudaFuncAttributeMaxDynamicSharedMemorySize,
                         GEMM_SMEM);

    rope_table_kernel<<<(N_SEQ * 32 + 255) / 256, 256>>>();
    rmsnorm_cvt_kernel<<<N_SEQ, 256>>>(seq, g, ahi, alo);
    transpose_cvt_kernel<<<dim3(QKVC / 32, DMODEL / 32), dim3(32, 8)>>>(
        w_qkv, DMODEL, QKVC, wqh, wql);
    transpose_cvt_kernel<<<dim3(DMODEL / 32, DINNER / 32), dim3(32, 8)>>>(
        w_out, DINNER, DMODEL, woh, wol);

    // QKV GEMM with fused table-RoPE on q,k columns (< 1024)
    gemm_sb16_kernel<<<dim3(QKVC / 128, N_SEQ / 128), 256, GEMM_SMEM>>>(
        ahi, alo, wqh, wql, qkvp, DMODEL, QKVC, 2 * DINNER);

    attn_kernel<<<dim3(N_SEQ / 64, HEADS), 128, ATTN_SMEM>>>(qkvp, athi, atlo);

    gemm_sb16_kernel<<<dim3(DMODEL / 128, N_SEQ / 128), 256, GEMM_SMEM>>>(
        athi, atlo, woh, wol, out, DINNER, DMODEL, 0);
}

// round 12
// speedup vs baseline: 1.0919x; 1.0506x over previous
#include <cuda_runtime.h>
#include <cuda_bf16.h>
#include <math.h>
#include <stdint.h>

#define N_SEQ   4096
#define DMODEL  1024
#define HEADS   8
#define DH      64
#define DINNER  512
#define QKVC    1536
#define WIN     128
#define NPERSIST 4

// ---------------- scratch (device globals; allocation-free rule) ------------
__device__ float2 g_rope[N_SEQ * 32];
__device__ __nv_bfloat16 g_a_hi[N_SEQ * DMODEL];
__device__ __nv_bfloat16 g_a_lo[N_SEQ * DMODEL];
__device__ __nv_bfloat16 g_wqkvT_hi[QKVC * DMODEL];
__device__ __nv_bfloat16 g_wqkvT_lo[QKVC * DMODEL];
__device__ __nv_bfloat16 g_woutT_hi[DMODEL * DINNER];
__device__ __nv_bfloat16 g_woutT_lo[DMODEL * DINNER];
__device__ __nv_bfloat16 g_q_hi[N_SEQ * DINNER];
__device__ __nv_bfloat16 g_q_lo[N_SEQ * DINNER];
__device__ __nv_bfloat16 g_k_hi[N_SEQ * DINNER];
__device__ __nv_bfloat16 g_k_lo[N_SEQ * DINNER];
__device__ __nv_bfloat16 g_v_hi[N_SEQ * DINNER];
__device__ __nv_bfloat16 g_v_lo[N_SEQ * DINNER];
__device__ __nv_bfloat16 g_attn_hi[N_SEQ * DINNER];
__device__ __nv_bfloat16 g_attn_lo[N_SEQ * DINNER];

// ---------------- helpers ----------------------------------------------
__device__ __forceinline__ uint32_t smem_u32(const void* p) {
    uint32_t a;
    asm("{ .reg .u64 t; cvta.to.shared.u64 t, %1; cvt.u32.u64 %0, t; }" : "=r"(a) : "l"(p));
    return a;
}
__device__ __forceinline__ void cp_async16(uint32_t dst, const void* src) {
    asm volatile("cp.async.cg.shared.global [%0], [%1], 16;" :: "r"(dst), "l"(src));
}
__device__ __forceinline__ void cp_commit() {
    asm volatile("cp.async.commit_group;" ::: "memory");
}
template <int N>
__device__ __forceinline__ void cp_wait() {
    asm volatile("cp.async.wait_group %0;" :: "n"(N) : "memory");
}
__device__ __forceinline__ void ldm_x4(uint32_t& r0, uint32_t& r1, uint32_t& r2,
                                       uint32_t& r3, uint32_t addr) {
    asm volatile("ldmatrix.sync.aligned.m8n8.x4.shared.b16 {%0,%1,%2,%3}, [%4];"
                 : "=r"(r0), "=r"(r1), "=r"(r2), "=r"(r3) : "r"(addr));
}
__device__ __forceinline__ void ldm_x4t(uint32_t& r0, uint32_t& r1, uint32_t& r2,
                                        uint32_t& r3, uint32_t addr) {
    asm volatile("ldmatrix.sync.aligned.m8n8.x4.trans.shared.b16 {%0,%1,%2,%3}, [%4];"
                 : "=r"(r0), "=r"(r1), "=r"(r2), "=r"(r3) : "r"(addr));
}
__device__ __forceinline__ void mma_bf16(float* d, const uint32_t* a, const uint32_t* b) {
    asm volatile("mma.sync.aligned.m16n8k16.row.col.f32.bf16.bf16.f32 "
                 "{%0,%1,%2,%3}, {%4,%5,%6,%7}, {%8,%9}, {%0,%1,%2,%3};"
                 : "+f"(d[0]), "+f"(d[1]), "+f"(d[2]), "+f"(d[3])
                 : "r"(a[0]), "r"(a[1]), "r"(a[2]), "r"(a[3]), "r"(b[0]), "r"(b[1]));
}
__device__ __forceinline__ void split_store(__nv_bfloat16* hp, __nv_bfloat16* lp,
                                            size_t off, float x, float y) {
    __nv_bfloat16 hx = __float2bfloat16(x), hy = __float2bfloat16(y);
    __nv_bfloat162 w;
    w.x = hx; w.y = hy;
    *(__nv_bfloat162*)(hp + off) = w;
    w.x = __float2bfloat16(x - __bfloat162float(hx));
    w.y = __float2bfloat16(y - __bfloat162float(hy));
    *(__nv_bfloat162*)(lp + off) = w;
}

// ---------------------------------------------------------------------------
// RoPE table
// ---------------------------------------------------------------------------
__global__ void rope_table_kernel() {
    int idx = blockIdx.x * blockDim.x + threadIdx.x;
    if (idx >= N_SEQ * 32) return;
    int n = idx >> 5;
    int t = idx & 31;
    float inv = (float)exp(-(double)t * (9.210340371976184 / 32.0));
    float s, c;
    sincosf((float)n * inv, &s, &c);
    g_rope[idx] = make_float2(c, s);
}

// ---------------------------------------------------------------------------
// RMSNorm -> bf16 hi/lo
// ---------------------------------------------------------------------------
__global__ void rmsnorm_cvt_kernel(const float* __restrict__ seq,
                                   const float* __restrict__ g,
                                   __nv_bfloat16* __restrict__ hi,
                                   __nv_bfloat16* __restrict__ lo) {
    int row = blockIdx.x;
    int t = threadIdx.x;
    float4 v = ((const float4*)(seq + row * DMODEL))[t];
    float ss = v.x * v.x + v.y * v.y + v.z * v.z + v.w * v.w;
#pragma unroll
    for (int o = 16; o > 0; o >>= 1) ss += __shfl_xor_sync(0xffffffffu, ss, o);
    __shared__ float ws[8];
    if ((t & 31) == 0) ws[t >> 5] = ss;
    __syncthreads();
    float tot = ws[0] + ws[1] + ws[2] + ws[3] + ws[4] + ws[5] + ws[6] + ws[7];
    float inv = rsqrtf(tot * (1.0f / (float)DMODEL) + 1.1920929e-07f);
    float4 gv = ((const float4*)g)[t];
    size_t base = (size_t)row * DMODEL + t * 4;
    split_store(hi, lo, base, v.x * inv * gv.x, v.y * inv * gv.y);
    split_store(hi, lo, base + 2, v.z * inv * gv.z, v.w * inv * gv.w);
}

// ---------------------------------------------------------------------------
// Transpose + bf16 hi/lo split: src[K][N] -> dst[N][K]
// ---------------------------------------------------------------------------
__global__ void transpose_cvt_kernel(const float* __restrict__ src, int K, int N,
                                     __nv_bfloat16* __restrict__ hi,
                                     __nv_bfloat16* __restrict__ lo) {
    __shared__ float tile[32][33];
    int bx = blockIdx.x, by = blockIdx.y;
    int tx = threadIdx.x, ty = threadIdx.y;
#pragma unroll
    for (int i = 0; i < 4; i++) {
        int k = by * 32 + ty + 8 * i;
        int n = bx * 32 + tx;
        tile[ty + 8 * i][tx] = src[(size_t)k * N + n];
    }
    __syncthreads();
#pragma unroll
    for (int i = 0; i < 4; i++) {
        int n = bx * 32 + ty + 8 * i;
        int k = by * 32 + tx;
        float v = tile[tx][ty + 8 * i];
        __nv_bfloat16 h = __float2bfloat16(v);
        hi[(size_t)n * K + k] = h;
        lo[(size_t)n * K + k] = __float2bfloat16(v - __bfloat162float(h));
    }
}

// ---------------------------------------------------------------------------
// Split-bf16 GEMM via mma.sync. Two epilogue modes:
//   qkv mode (qh != nullptr): apply table RoPE to cols<1024, split result to
//     bf16 hi/lo planes q/k/v (col section = col>>9, col within = col&511)
//   out mode: plain fp32 store to C.
// ---------------------------------------------------------------------------
#define GEMM_SMEM (2 * 4 * 16384)

struct Frag {
    uint32_t ah[4][4], al[4][4], bh[4][2], bl[4][2];
};

__global__ __launch_bounds__(256, 1)
void gemm_sb16_kernel(const __nv_bfloat16* __restrict__ Ahi,
                      const __nv_bfloat16* __restrict__ Alo,
                      const __nv_bfloat16* __restrict__ Bhi,
                      const __nv_bfloat16* __restrict__ Blo,
                      float* __restrict__ C, int K, int ldc,
                      __nv_bfloat16* qh, __nv_bfloat16* ql,
                      __nv_bfloat16* kh, __nv_bfloat16* kl,
                      __nv_bfloat16* vh, __nv_bfloat16* vl) {
    extern __shared__ char smem[];
    uint32_t sb = smem_u32(smem);
    int tid = threadIdx.x;
    int wid = tid >> 5, lane = tid & 31;
    int m0 = blockIdx.y * 128, n0 = blockIdx.x * 128;
    int wm = wid & 1;
    int wn = wid >> 1;

    auto prefetch = [&](int c, int buf) {
        int kc = c << 6;
        uint32_t b32 = sb + buf * 65536;
#pragma unroll
        for (int i = 0; i < 4; i++) {
            int idx = tid + 256 * i;
            int r = idx >> 3, u = idx & 7;
            uint32_t dst = b32 + r * 128 + ((u ^ (r & 7)) << 4);
            size_t ga = (size_t)(m0 + r) * K + kc + u * 8;
            size_t gb = (size_t)(n0 + r) * K + kc + u * 8;
            cp_async16(dst,         Ahi + ga);
            cp_async16(dst + 16384, Alo + ga);
            cp_async16(dst + 32768, Bhi + gb);
            cp_async16(dst + 49152, Blo + gb);
        }
        cp_commit();
    };

    auto load_frags = [&](uint32_t b32, int ks, Frag& f) {
#pragma unroll
        for (int mt = 0; mt < 4; mt++) {
            int r = wm * 64 + mt * 16 + (lane & 15);
            int u = 2 * ks + (lane >> 4);
            uint32_t addr = b32 + r * 128 + ((u ^ (r & 7)) << 4);
            ldm_x4(f.ah[mt][0], f.ah[mt][1], f.ah[mt][2], f.ah[mt][3], addr);
            ldm_x4(f.al[mt][0], f.al[mt][1], f.al[mt][2], f.al[mt][3], addr + 16384);
        }
#pragma unroll
        for (int np = 0; np < 2; np++) {
            int r = wn * 32 + np * 16 + (lane & 15);
            int u = 2 * ks + (lane >> 4);
            uint32_t addr = b32 + 32768 + r * 128 + ((u ^ (r & 7)) << 4);
            uint32_t t0, t1, t2, t3;
            ldm_x4(t0, t1, t2, t3, addr);
            f.bh[2 * np][0] = t0; f.bh[2 * np][1] = t2;
            f.bh[2 * np + 1][0] = t1; f.bh[2 * np + 1][1] = t3;
            ldm_x4(t0, t1, t2, t3, addr + 16384);
            f.bl[2 * np][0] = t0; f.bl[2 * np][1] = t2;
            f.bl[2 * np + 1][0] = t1; f.bl[2 * np + 1][1] = t3;
        }
    };

    float acc[4][4][4];
#pragma unroll
    for (int i = 0; i < 4; i++)
#pragma unroll
        for (int j = 0; j < 4; j++)
#pragma unroll
            for (int k = 0; k < 4; k++) acc[i][j][k] = 0.f;

    int NC = K >> 6;
    prefetch(0, 0);

    Frag f0, f1;
    for (int c = 0; c < NC; c++) {
        int buf = c & 1;
        if (c + 1 < NC) {
            prefetch(c + 1, buf ^ 1);
            cp_wait<1>();
        } else {
            cp_wait<0>();
        }
        __syncthreads();

        uint32_t b32 = sb + buf * 65536;
        load_frags(b32, 0, f0);
#pragma unroll
        for (int ks = 0; ks < 4; ks++) {
            Frag& cur = (ks & 1) ? f1 : f0;
            Frag& nxt = (ks & 1) ? f0 : f1;
            if (ks < 3) load_frags(b32, ks + 1, nxt);
#pragma unroll
            for (int mt = 0; mt < 4; mt++)
#pragma unroll
                for (int nt = 0; nt < 4; nt++) {
                    mma_bf16(acc[mt][nt], cur.ah[mt], cur.bh[nt]);
                    mma_bf16(acc[mt][nt], cur.ah[mt], cur.bl[nt]);
                    mma_bf16(acc[mt][nt], cur.al[mt], cur.bh[nt]);
                }
        }
        __syncthreads();
    }

    int rbase = m0 + wm * 64 + (lane >> 2);
    int cbase = n0 + wn * 32 + (lane & 3) * 2;
    bool qkv_mode = (qh != nullptr);

#pragma unroll
    for (int mt = 0; mt < 4; mt++)
#pragma unroll
        for (int nt = 0; nt < 4; nt++) {
            int row = rbase + mt * 16;
            int col = cbase + nt * 8;
            float2 v0 = make_float2(acc[mt][nt][0], acc[mt][nt][1]);
            float2 v1 = make_float2(acc[mt][nt][2], acc[mt][nt][3]);
            if (qkv_mode) {
                if (col < 2 * DINNER) {  // RoPE on q,k
                    int t = (col & 63) >> 1;
                    float2 cs0 = g_rope[row * 32 + t];
                    float2 cs1 = g_rope[(row + 8) * 32 + t];
                    float a = v0.x, b = v0.y;
                    v0.x = a * cs0.x - b * cs0.y;
                    v0.y = b * cs0.x + a * cs0.y;
                    a = v1.x; b = v1.y;
                    v1.x = a * cs1.x - b * cs1.y;
                    v1.y = b * cs1.x + a * cs1.y;
                }
                int sec = col >> 9;
                __nv_bfloat16 *hp, *lp;
                if (sec == 0) { hp = qh; lp = ql; }
                else if (sec == 1) { hp = kh; lp = kl; }
                else { hp = vh; lp = vl; }
                int cc = col & 511;
                split_store(hp, lp, (size_t)row * DINNER + cc, v0.x, v0.y);
                split_store(hp, lp, (size_t)(row + 8) * DINNER + cc, v1.x, v1.y);
            } else {
                *(float2*)(C + (size_t)row * ldc + col) = v0;
                *(float2*)(C + (size_t)(row + 8) * ldc + col) = v1;
            }
        }
}

// ---------------------------------------------------------------------------
// Tensor-core attention: per block 64 queries x 1 head; 4 warps x 16 queries.
// S = Q*K^T via split-bf16 3-term HMMA; online softmax in acc layout; P packed
// bf16 hi/lo to per-warp SMEM; O = P*V via HMMA with ldmatrix.trans V frags.
// ---------------------------------------------------------------------------
#define AQ_H 0
#define AQ_L 8192
#define AK_H 16384
#define AK_L 49152
#define AV_H 81920
#define AV_L 114688
#define AP   147456
#define ATTN_SMEM 163840
#define NEGINF (-1e30f)

__global__ __launch_bounds__(128) void attn_kernel(
    const __nv_bfloat16* __restrict__ qh_g, const __nv_bfloat16* __restrict__ ql_g,
    const __nv_bfloat16* __restrict__ kh_g, const __nv_bfloat16* __restrict__ kl_g,
    const __nv_bfloat16* __restrict__ vh_g, const __nv_bfloat16* __restrict__ vl_g,
    __nv_bfloat16* __restrict__ out_hi, __nv_bfloat16* __restrict__ out_lo) {
    extern __shared__ char smem[];
    uint32_t sb = smem_u32(smem);
    int h = blockIdx.y;
    int qs = blockIdx.x * 64;
    int tid = threadIdx.x;
    int warp = tid >> 5, lane = tid & 31;

    int kv_lo = qs - WIN; if (kv_lo < 0) kv_lo = 0;
    int cnt = qs + 64 - kv_lo;
    int P = (kv_lo > 0) ? NPERSIST : 0;
    int tot = cnt + P;

    // stage Q (64 rows x 8 units)
    for (int idx = tid; idx < 512; idx += 128) {
        int r = idx >> 3, u = idx & 7;
        size_t s = (size_t)(qs + r) * DINNER + h * DH + u * 8;
        int d = r * 128 + ((u ^ (r & 7)) << 4);
        *(float4*)(smem + AQ_H + d) = *(const float4*)(qh_g + s);
        *(float4*)(smem + AQ_L + d) = *(const float4*)(ql_g + s);
    }
    // stage K/V (256 rows x 8 units, zero-padded beyond tot)
    float4 z = make_float4(0.f, 0.f, 0.f, 0.f);
    for (int idx = tid; idx < 2048; idx += 128) {
        int r = idx >> 3, u = idx & 7;
        int d = r * 128 + ((u ^ (r & 7)) << 4);
        if (r < tot) {
            int gk = (r < cnt) ? (kv_lo + r) : (r - cnt);
            size_t s = (size_t)gk * DINNER + h * DH + u * 8;
            *(float4*)(smem + AK_H + d) = *(const float4*)(kh_g + s);
            *(float4*)(smem + AK_L + d) = *(const float4*)(kl_g + s);
            *(float4*)(smem + AV_H + d) = *(const float4*)(vh_g + s);
            *(float4*)(smem + AV_L + d) = *(const float4*)(vl_g + s);
        } else {
            *(float4*)(smem + AK_H + d) = z;
            *(float4*)(smem + AK_L + d) = z;
            *(float4*)(smem + AV_H + d) = z;
            *(float4*)(smem + AV_L + d) = z;
        }
    }
    __syncthreads();

    // Q fragments (persistent)
    uint32_t qfh[4][4], qfl[4][4];
    {
        int row = warp * 16 + (lane & 15);
#pragma unroll
        for (int ks = 0; ks < 4; ks++) {
            uint32_t a = sb + AQ_H + row * 128 + (((2 * ks + (lane >> 4)) ^ (row & 7)) << 4);
            ldm_x4(qfh[ks][0], qfh[ks][1], qfh[ks][2], qfh[ks][3], a);
            ldm_x4(qfl[ks][0], qfl[ks][1], qfl[ks][2], qfl[ks][3], a + 8192);
        }
    }

    float oacc[8][4];
#pragma unroll
    for (int i = 0; i < 8; i++)
#pragma unroll
        for (int j = 0; j < 4; j++) oacc[i][j] = 0.f;

    float m0 = NEGINF, m1 = NEGINF, l0 = 0.f, l1 = 0.f;
    int rowq0 = qs + warp * 16 + (lane >> 2);
    int rowq1 = rowq0 + 8;
    int pbase = AP + warp * 4096;
    int nch = (tot + 63) >> 6;

    for (int ch = 0; ch < nch; ch++) {
        float sacc[8][4];
#pragma unroll
        for (int i = 0; i < 8; i++)
#pragma unroll
            for (int j = 0; j < 4; j++) sacc[i][j] = 0.f;

#pragma unroll
        for (int ks = 0; ks < 4; ks++) {
            uint32_t kbh[8][2], kbl[8][2];
#pragma unroll
            for (int np = 0; np < 4; np++) {
                int r = ch * 64 + np * 16 + (lane & 15);
                uint32_t a = sb + AK_H + r * 128 + (((2 * ks + (lane >> 4)) ^ (r & 7)) << 4);
                uint32_t t0, t1, t2, t3;
                ldm_x4(t0, t1, t2, t3, a);
                kbh[2 * np][0] = t0; kbh[2 * np][1] = t2;
                kbh[2 * np + 1][0] = t1; kbh[2 * np + 1][1] = t3;
                ldm_x4(t0, t1, t2, t3, a + 32768);
                kbl[2 * np][0] = t0; kbl[2 * np][1] = t2;
                kbl[2 * np + 1][0] = t1; kbl[2 * np + 1][1] = t3;
            }
#pragma unroll
            for (int nt = 0; nt < 8; nt++) {
                mma_bf16(sacc[nt], qfh[ks], kbh[nt]);
                mma_bf16(sacc[nt], qfh[ks], kbl[nt]);
                mma_bf16(sacc[nt], qfl[ks], kbh[nt]);
            }
        }

        // mask + scale + chunk max
        float cm0 = NEGINF, cm1 = NEGINF;
#pragma unroll
        for (int nt = 0; nt < 8; nt++)
#pragma unroll
            for (int j = 0; j < 4; j++) {
                int key = ch * 64 + nt * 8 + 2 * (lane & 3) + (j & 1);
                int rq = (j < 2) ? rowq0 : rowq1;
                bool ok;
                if (key >= tot) ok = false;
                else if (key < cnt) {
                    int gk = kv_lo + key;
                    ok = (gk <= rq) && ((rq - gk <= WIN) || (gk < NPERSIST));
                } else ok = true;
                float s = ok ? sacc[nt][j] * 0.125f : NEGINF;
                sacc[nt][j] = s;
                if (j < 2) cm0 = fmaxf(cm0, s); else cm1 = fmaxf(cm1, s);
            }
        cm0 = fmaxf(cm0, __shfl_xor_sync(0xffffffffu, cm0, 1));
        cm0 = fmaxf(cm0, __shfl_xor_sync(0xffffffffu, cm0, 2));
        cm1 = fmaxf(cm1, __shfl_xor_sync(0xffffffffu, cm1, 1));
        cm1 = fmaxf(cm1, __shfl_xor_sync(0xffffffffu, cm1, 2));
        float nm0 = fmaxf(m0, cm0), nm1 = fmaxf(m1, cm1);
        float c0 = __expf(m0 - nm0), c1 = __expf(m1 - nm1);
        m0 = nm0; m1 = nm1;

        __syncwarp();
        // p = exp(s - m), pack hi/lo to SMEM, row sums
        float sum0 = 0.f, sum1 = 0.f;
        int r0 = lane >> 2, r1 = r0 + 8;
        int ioff = 4 * (lane & 3);
#pragma unroll
        for (int nt = 0; nt < 8; nt++) {
            float p0 = __expf(sacc[nt][0] - m0);
            float p1 = __expf(sacc[nt][1] - m0);
            float p2 = __expf(sacc[nt][2] - m1);
            float p3 = __expf(sacc[nt][3] - m1);
            sum0 += p0 + p1;
            sum1 += p2 + p3;
            int a0 = pbase + r0 * 128 + ((nt ^ (r0 & 7)) << 4) + ioff;
            int a1 = pbase + r1 * 128 + ((nt ^ (r1 & 7)) << 4) + ioff;
            __nv_bfloat16 h0 = __float2bfloat16(p0), h1 = __float2bfloat16(p1);
            __nv_bfloat16 h2 = __float2bfloat16(p2), h3 = __float2bfloat16(p3);
            __nv_bfloat162 w;
            w.x = h0; w.y = h1; *(__nv_bfloat162*)(smem + a0) = w;
            w.x = h2; w.y = h3; *(__nv_bfloat162*)(smem + a1) = w;
            w.x = __float2bfloat16(p0 - __bfloat162float(h0));
            w.y = __float2bfloat16(p1 - __bfloat162float(h1));
            *(__nv_bfloat162*)(smem + a0 + 2048) = w;
            w.x = __float2bfloat16(p2 - __bfloat162float(h2));
            w.y = __float2bfloat16(p3 - __bfloat162float(h3));
            *(__nv_bfloat162*)(smem + a1 + 2048) = w;
        }
        sum0 += __shfl_xor_sync(0xffffffffu, sum0, 1);
        sum0 += __shfl_xor_sync(0xffffffffu, sum0, 2);
        sum1 += __shfl_xor_sync(0xffffffffu, sum1, 1);
        sum1 += __shfl_xor_sync(0xffffffffu, sum1, 2);
        l0 = l0 * c0 + sum0;
        l1 = l1 * c1 + sum1;

        // rescale O
#pragma unroll
        for (int dt = 0; dt < 8; dt++) {
            oacc[dt][0] *= c0; oacc[dt][1] *= c0;
            oacc[dt][2] *= c1; oacc[dt][3] *= c1;
        }
        __syncwarp();

        // P*V
        int vk = tot - ch * 64; if (vk > 64) vk = 64;
        int kpv = (vk + 15) >> 4;
        for (int kp = 0; kp < kpv; kp++) {
            uint32_t pfh[4], pfl[4];
            {
                int row = lane & 15;
                uint32_t a = sb + pbase + row * 128 + (((2 * kp + (lane >> 4)) ^ (row & 7)) << 4);
                ldm_x4(pfh[0], pfh[1], pfh[2], pfh[3], a);
                ldm_x4(pfl[0], pfl[1], pfl[2], pfl[3], a + 2048);
            }
            uint32_t vbh[8][2], vbl[8][2];
#pragma unroll
            for (int np = 0; np < 4; np++) {
                int r = ch * 64 + kp * 16 + (lane & 7) + (((lane >> 4) & 1) << 3);
                int u = np * 2 + ((lane >> 3) & 1);
                uint32_t a = sb + AV_H + r * 128 + ((u ^ (r & 7)) << 4);
                uint32_t t0, t1, t2, t3;
                ldm_x4t(t0, t1, t2, t3, a);
                vbh[2 * np][0] = t0; vbh[2 * np][1] = t2;
                vbh[2 * np + 1][0] = t1; vbh[2 * np + 1][1] = t3;
                ldm_x4t(t0, t1, t2, t3, a + 32768);
                vbl[2 * np][0] = t0; vbl[2 * np][1] = t2;
                vbl[2 * np + 1][0] = t1; vbl[2 * np + 1][1] = t3;
            }
#pragma unroll
            for (int dt = 0; dt < 8; dt++) {
                mma_bf16(oacc[dt], pfh, vbh[dt]);
                mma_bf16(oacc[dt], pfh, vbl[dt]);
                mma_bf16(oacc[dt], pfl, vbh[dt]);
            }
        }
        __syncwarp();
    }

    float i0 = 1.0f / l0, i1 = 1.0f / l1;
#pragma unroll
    for (int dt = 0; dt < 8; dt++) {
        int col = h * DH + dt * 8 + 2 * (lane & 3);
        split_store(out_hi, out_lo, (size_t)rowq0 * DINNER + col,
                    oacc[dt][0] * i0, oacc[dt][1] * i0);
        split_store(out_hi, out_lo, (size_t)rowq1 * DINNER + col,
                    oacc[dt][2] * i1, oacc[dt][3] * i1);
    }
}

// ---------------------------------------------------------------------------
extern "C" void kernel_launch(void* const* d_in, const int* in_sizes, int n_in,
                              void* d_out, int out_size) {
    const float* seq   = (const float*)d_in[0];
    const float* g     = (const float*)d_in[1];
    const float* w_qkv = (const float*)d_in[2];
    const float* w_out = (const float*)d_in[3];
    float* out = (float*)d_out;

    __nv_bfloat16 *ahi, *alo, *wqh, *wql, *woh, *wol, *athi, *atlo;
    __nv_bfloat16 *qh, *ql, *kh, *kl, *vh, *vl;
    cudaGetSymbolAddress((void**)&ahi, g_a_hi);
    cudaGetSymbolAddress((void**)&alo, g_a_lo);
    cudaGetSymbolAddress((void**)&wqh, g_wqkvT_hi);
    cudaGetSymbolAddress((void**)&wql, g_wqkvT_lo);
    cudaGetSymbolAddress((void**)&woh, g_woutT_hi);
    cudaGetSymbolAddress((void**)&wol, g_woutT_lo);
    cudaGetSymbolAddress((void**)&athi, g_attn_hi);
    cudaGetSymbolAddress((void**)&atlo, g_attn_lo);
    cudaGetSymbolAddress((void**)&qh, g_q_hi);
    cudaGetSymbolAddress((void**)&ql, g_q_lo);
    cudaGetSymbolAddress((void**)&kh, g_k_hi);
    cudaGetSymbolAddress((void**)&kl, g_k_lo);
    cudaGetSymbolAddress((void**)&vh, g_v_hi);
    cudaGetSymbolAddress((void**)&vl, g_v_lo);

    cudaFuncSetAttribute(attn_kernel, cudaFuncAttributeMaxDynamicSharedMemorySize,
                         ATTN_SMEM);
    cudaFuncSetAttribute(gemm_sb16_kernel, cudaFuncAttributeMaxDynamicSharedMemorySize,
                         GEMM_SMEM);

    rope_table_kernel<<<(N_SEQ * 32 + 255) / 256, 256>>>();
    rmsnorm_cvt_kernel<<<N_SEQ, 256>>>(seq, g, ahi, alo);
    transpose_cvt_kernel<<<dim3(QKVC / 32, DMODEL / 32), dim3(32, 8)>>>(
        w_qkv, DMODEL, QKVC, wqh, wql);
    transpose_cvt_kernel<<<dim3(DMODEL / 32, DINNER / 32), dim3(32, 8)>>>(
        w_out, DINNER, DMODEL, woh, wol);

    // QKV GEMM: fused RoPE + split to q/k/v bf16 hi/lo planes
    gemm_sb16_kernel<<<dim3(QKVC / 128, N_SEQ / 128), 256, GEMM_SMEM>>>(
        ahi, alo, wqh, wql, nullptr, DMODEL, QKVC, qh, ql, kh, kl, vh, vl);

    attn_kernel<<<dim3(N_SEQ / 64, HEADS), 128, ATTN_SMEM>>>(
        qh, ql, kh, kl, vh, vl, athi, atlo);

    gemm_sb16_kernel<<<dim3(DMODEL / 128, N_SEQ / 128), 256, GEMM_SMEM>>>(
        athi, atlo, woh, wol, out, DINNER, DMODEL,
        nullptr, nullptr, nullptr, nullptr, nullptr, nullptr);
}

// round 13
// speedup vs baseline: 1.2329x; 1.1292x over previous
#include <cuda_runtime.h>
#include <cuda_bf16.h>
#include <math.h>
#include <stdint.h>

#define N_SEQ   4096
#define DMODEL  1024
#define HEADS   8
#define DH      64
#define DINNER  512
#define QKVC    1536
#define WIN     128
#define NPERSIST 4

// ---------------- scratch (device globals; allocation-free rule) ------------
__device__ float2 g_rope[N_SEQ * 32];
__device__ __nv_bfloat16 g_a_hi[N_SEQ * DMODEL];
__device__ __nv_bfloat16 g_a_lo[N_SEQ * DMODEL];
__device__ __nv_bfloat16 g_wqkvT_hi[QKVC * DMODEL];
__device__ __nv_bfloat16 g_wqkvT_lo[QKVC * DMODEL];
__device__ __nv_bfloat16 g_woutT_hi[DMODEL * DINNER];
__device__ __nv_bfloat16 g_woutT_lo[DMODEL * DINNER];
__device__ __nv_bfloat16 g_q_hi[N_SEQ * DINNER];
__device__ __nv_bfloat16 g_q_lo[N_SEQ * DINNER];
__device__ __nv_bfloat16 g_k_hi[N_SEQ * DINNER];
__device__ __nv_bfloat16 g_k_lo[N_SEQ * DINNER];
__device__ __nv_bfloat16 g_v_hi[N_SEQ * DINNER];
__device__ __nv_bfloat16 g_v_lo[N_SEQ * DINNER];
__device__ __nv_bfloat16 g_attn_hi[N_SEQ * DINNER];
__device__ __nv_bfloat16 g_attn_lo[N_SEQ * DINNER];

template <int N> struct IC { static constexpr int value = N; };

// ---------------- helpers ----------------------------------------------
__device__ __forceinline__ uint32_t smem_u32(const void* p) {
    uint32_t a;
    asm("{ .reg .u64 t; cvta.to.shared.u64 t, %1; cvt.u32.u64 %0, t; }" : "=r"(a) : "l"(p));
    return a;
}
__device__ __forceinline__ void cp_async16(uint32_t dst, const void* src) {
    asm volatile("cp.async.cg.shared.global [%0], [%1], 16;" :: "r"(dst), "l"(src));
}
__device__ __forceinline__ void cp_commit() {
    asm volatile("cp.async.commit_group;" ::: "memory");
}
template <int N>
__device__ __forceinline__ void cp_wait() {
    asm volatile("cp.async.wait_group %0;" :: "n"(N) : "memory");
}
__device__ __forceinline__ void ldm_x4(uint32_t& r0, uint32_t& r1, uint32_t& r2,
                                       uint32_t& r3, uint32_t addr) {
    asm volatile("ldmatrix.sync.aligned.m8n8.x4.shared.b16 {%0,%1,%2,%3}, [%4];"
                 : "=r"(r0), "=r"(r1), "=r"(r2), "=r"(r3) : "r"(addr));
}
__device__ __forceinline__ void ldm_x4t(uint32_t& r0, uint32_t& r1, uint32_t& r2,
                                        uint32_t& r3, uint32_t addr) {
    asm volatile("ldmatrix.sync.aligned.m8n8.x4.trans.shared.b16 {%0,%1,%2,%3}, [%4];"
                 : "=r"(r0), "=r"(r1), "=r"(r2), "=r"(r3) : "r"(addr));
}
__device__ __forceinline__ void mma_bf16(float* d, const uint32_t* a, const uint32_t* b) {
    asm volatile("mma.sync.aligned.m16n8k16.row.col.f32.bf16.bf16.f32 "
                 "{%0,%1,%2,%3}, {%4,%5,%6,%7}, {%8,%9}, {%0,%1,%2,%3};"
                 : "+f"(d[0]), "+f"(d[1]), "+f"(d[2]), "+f"(d[3])
                 : "r"(a[0]), "r"(a[1]), "r"(a[2]), "r"(a[3]), "r"(b[0]), "r"(b[1]));
}
__device__ __forceinline__ void split_store(__nv_bfloat16* hp, __nv_bfloat16* lp,
                                            size_t off, float x, float y) {
    __nv_bfloat16 hx = __float2bfloat16(x), hy = __float2bfloat16(y);
    __nv_bfloat162 w;
    w.x = hx; w.y = hy;
    *(__nv_bfloat162*)(hp + off) = w;
    w.x = __float2bfloat16(x - __bfloat162float(hx));
    w.y = __float2bfloat16(y - __bfloat162float(hy));
    *(__nv_bfloat162*)(lp + off) = w;
}

// ---------------------------------------------------------------------------
// RoPE table
// ---------------------------------------------------------------------------
__global__ void rope_table_kernel() {
    int idx = blockIdx.x * blockDim.x + threadIdx.x;
    if (idx >= N_SEQ * 32) return;
    int n = idx >> 5;
    int t = idx & 31;
    float inv = (float)exp(-(double)t * (9.210340371976184 / 32.0));
    float s, c;
    sincosf((float)n * inv, &s, &c);
    g_rope[idx] = make_float2(c, s);
}

// ---------------------------------------------------------------------------
// RMSNorm -> bf16 hi/lo
// ---------------------------------------------------------------------------
__global__ void rmsnorm_cvt_kernel(const float* __restrict__ seq,
                                   const float* __restrict__ g,
                                   __nv_bfloat16* __restrict__ hi,
                                   __nv_bfloat16* __restrict__ lo) {
    int row = blockIdx.x;
    int t = threadIdx.x;
    float4 v = ((const float4*)(seq + row * DMODEL))[t];
    float ss = v.x * v.x + v.y * v.y + v.z * v.z + v.w * v.w;
#pragma unroll
    for (int o = 16; o > 0; o >>= 1) ss += __shfl_xor_sync(0xffffffffu, ss, o);
    __shared__ float ws[8];
    if ((t & 31) == 0) ws[t >> 5] = ss;
    __syncthreads();
    float tot = ws[0] + ws[1] + ws[2] + ws[3] + ws[4] + ws[5] + ws[6] + ws[7];
    float inv = rsqrtf(tot * (1.0f / (float)DMODEL) + 1.1920929e-07f);
    float4 gv = ((const float4*)g)[t];
    size_t base = (size_t)row * DMODEL + t * 4;
    split_store(hi, lo, base, v.x * inv * gv.x, v.y * inv * gv.y);
    split_store(hi, lo, base + 2, v.z * inv * gv.z, v.w * inv * gv.w);
}

// ---------------------------------------------------------------------------
// Transpose + bf16 hi/lo split: src[K][N] -> dst[N][K]
// ---------------------------------------------------------------------------
__global__ void transpose_cvt_kernel(const float* __restrict__ src, int K, int N,
                                     __nv_bfloat16* __restrict__ hi,
                                     __nv_bfloat16* __restrict__ lo) {
    __shared__ float tile[32][33];
    int bx = blockIdx.x, by = blockIdx.y;
    int tx = threadIdx.x, ty = threadIdx.y;
#pragma unroll
    for (int i = 0; i < 4; i++) {
        int k = by * 32 + ty + 8 * i;
        int n = bx * 32 + tx;
        tile[ty + 8 * i][tx] = src[(size_t)k * N + n];
    }
    __syncthreads();
#pragma unroll
    for (int i = 0; i < 4; i++) {
        int n = bx * 32 + ty + 8 * i;
        int k = by * 32 + tx;
        float v = tile[tx][ty + 8 * i];
        __nv_bfloat16 h = __float2bfloat16(v);
        hi[(size_t)n * K + k] = h;
        lo[(size_t)n * K + k] = __float2bfloat16(v - __bfloat162float(h));
    }
}

// ---------------------------------------------------------------------------
// Split-bf16 GEMM via mma.sync (unchanged from round 12).
// ---------------------------------------------------------------------------
#define GEMM_SMEM (2 * 4 * 16384)

struct Frag {
    uint32_t ah[4][4], al[4][4], bh[4][2], bl[4][2];
};

__global__ __launch_bounds__(256, 1)
void gemm_sb16_kernel(const __nv_bfloat16* __restrict__ Ahi,
                      const __nv_bfloat16* __restrict__ Alo,
                      const __nv_bfloat16* __restrict__ Bhi,
                      const __nv_bfloat16* __restrict__ Blo,
                      float* __restrict__ C, int K, int ldc,
                      __nv_bfloat16* qh, __nv_bfloat16* ql,
                      __nv_bfloat16* kh, __nv_bfloat16* kl,
                      __nv_bfloat16* vh, __nv_bfloat16* vl) {
    extern __shared__ char smem[];
    uint32_t sb = smem_u32(smem);
    int tid = threadIdx.x;
    int wid = tid >> 5, lane = tid & 31;
    int m0 = blockIdx.y * 128, n0 = blockIdx.x * 128;
    int wm = wid & 1;
    int wn = wid >> 1;

    auto prefetch = [&](int c, int buf) {
        int kc = c << 6;
        uint32_t b32 = sb + buf * 65536;
#pragma unroll
        for (int i = 0; i < 4; i++) {
            int idx = tid + 256 * i;
            int r = idx >> 3, u = idx & 7;
            uint32_t dst = b32 + r * 128 + ((u ^ (r & 7)) << 4);
            size_t ga = (size_t)(m0 + r) * K + kc + u * 8;
            size_t gb = (size_t)(n0 + r) * K + kc + u * 8;
            cp_async16(dst,         Ahi + ga);
            cp_async16(dst + 16384, Alo + ga);
            cp_async16(dst + 32768, Bhi + gb);
            cp_async16(dst + 49152, Blo + gb);
        }
        cp_commit();
    };

    auto load_frags = [&](uint32_t b32, int ks, Frag& f) {
#pragma unroll
        for (int mt = 0; mt < 4; mt++) {
            int r = wm * 64 + mt * 16 + (lane & 15);
            int u = 2 * ks + (lane >> 4);
            uint32_t addr = b32 + r * 128 + ((u ^ (r & 7)) << 4);
            ldm_x4(f.ah[mt][0], f.ah[mt][1], f.ah[mt][2], f.ah[mt][3], addr);
            ldm_x4(f.al[mt][0], f.al[mt][1], f.al[mt][2], f.al[mt][3], addr + 16384);
        }
#pragma unroll
        for (int np = 0; np < 2; np++) {
            int r = wn * 32 + np * 16 + (lane & 15);
            int u = 2 * ks + (lane >> 4);
            uint32_t addr = b32 + 32768 + r * 128 + ((u ^ (r & 7)) << 4);
            uint32_t t0, t1, t2, t3;
            ldm_x4(t0, t1, t2, t3, addr);
            f.bh[2 * np][0] = t0; f.bh[2 * np][1] = t2;
            f.bh[2 * np + 1][0] = t1; f.bh[2 * np + 1][1] = t3;
            ldm_x4(t0, t1, t2, t3, addr + 16384);
            f.bl[2 * np][0] = t0; f.bl[2 * np][1] = t2;
            f.bl[2 * np + 1][0] = t1; f.bl[2 * np + 1][1] = t3;
        }
    };

    float acc[4][4][4];
#pragma unroll
    for (int i = 0; i < 4; i++)
#pragma unroll
        for (int j = 0; j < 4; j++)
#pragma unroll
            for (int k = 0; k < 4; k++) acc[i][j][k] = 0.f;

    int NC = K >> 6;
    prefetch(0, 0);

    Frag f0, f1;
    for (int c = 0; c < NC; c++) {
        int buf = c & 1;
        if (c + 1 < NC) {
            prefetch(c + 1, buf ^ 1);
            cp_wait<1>();
        } else {
            cp_wait<0>();
        }
        __syncthreads();

        uint32_t b32 = sb + buf * 65536;
        load_frags(b32, 0, f0);
#pragma unroll
        for (int ks = 0; ks < 4; ks++) {
            Frag& cur = (ks & 1) ? f1 : f0;
            Frag& nxt = (ks & 1) ? f0 : f1;
            if (ks < 3) load_frags(b32, ks + 1, nxt);
#pragma unroll
            for (int mt = 0; mt < 4; mt++)
#pragma unroll
                for (int nt = 0; nt < 4; nt++) {
                    mma_bf16(acc[mt][nt], cur.ah[mt], cur.bh[nt]);
                    mma_bf16(acc[mt][nt], cur.ah[mt], cur.bl[nt]);
                    mma_bf16(acc[mt][nt], cur.al[mt], cur.bh[nt]);
                }
        }
        __syncthreads();
    }

    int rbase = m0 + wm * 64 + (lane >> 2);
    int cbase = n0 + wn * 32 + (lane & 3) * 2;
    bool qkv_mode = (qh != nullptr);

#pragma unroll
    for (int mt = 0; mt < 4; mt++)
#pragma unroll
        for (int nt = 0; nt < 4; nt++) {
            int row = rbase + mt * 16;
            int col = cbase + nt * 8;
            float2 v0 = make_float2(acc[mt][nt][0], acc[mt][nt][1]);
            float2 v1 = make_float2(acc[mt][nt][2], acc[mt][nt][3]);
            if (qkv_mode) {
                if (col < 2 * DINNER) {
                    int t = (col & 63) >> 1;
                    float2 cs0 = g_rope[row * 32 + t];
                    float2 cs1 = g_rope[(row + 8) * 32 + t];
                    float a = v0.x, b = v0.y;
                    v0.x = a * cs0.x - b * cs0.y;
                    v0.y = b * cs0.x + a * cs0.y;
                    a = v1.x; b = v1.y;
                    v1.x = a * cs1.x - b * cs1.y;
                    v1.y = b * cs1.x + a * cs1.y;
                }
                int sec = col >> 9;
                __nv_bfloat16 *hp, *lp;
                if (sec == 0) { hp = qh; lp = ql; }
                else if (sec == 1) { hp = kh; lp = kl; }
                else { hp = vh; lp = vl; }
                int cc = col & 511;
                split_store(hp, lp, (size_t)row * DINNER + cc, v0.x, v0.y);
                split_store(hp, lp, (size_t)(row + 8) * DINNER + cc, v1.x, v1.y);
            } else {
                *(float2*)(C + (size_t)row * ldc + col) = v0;
                *(float2*)(C + (size_t)(row + 8) * ldc + col) = v1;
            }
        }
}

// ---------------------------------------------------------------------------
// Tensor-core attention v2: 128 queries/block, 8 warps x 16 queries.
// Per-warp chunk bounds + 16-key mini chunk for persist keys.
// ---------------------------------------------------------------------------
#define AQ_H 0
#define AQ_L 16384
#define AK_H 32768
#define KV_STRIDE (272 * 128)
#define AK_L (AK_H + KV_STRIDE)
#define AV_H (AK_L + KV_STRIDE)
#define AV_L (AV_H + KV_STRIDE)
#define AP   (AV_L + KV_STRIDE)
#define ATTN_SMEM (AP + 8 * 4096)
#define NEGINF (-1e30f)

__global__ __launch_bounds__(256) void attn_kernel(
    const __nv_bfloat16* __restrict__ qh_g, const __nv_bfloat16* __restrict__ ql_g,
    const __nv_bfloat16* __restrict__ kh_g, const __nv_bfloat16* __restrict__ kl_g,
    const __nv_bfloat16* __restrict__ vh_g, const __nv_bfloat16* __restrict__ vl_g,
    __nv_bfloat16* __restrict__ out_hi, __nv_bfloat16* __restrict__ out_lo) {
    extern __shared__ char smem[];
    uint32_t sb = smem_u32(smem);
    int h = blockIdx.y;
    int qs = blockIdx.x * 128;
    int tid = threadIdx.x;
    int warp = tid >> 5, lane = tid & 31;

    int kv_lo = qs - WIN; if (kv_lo < 0) kv_lo = 0;
    int cnt = qs + 128 - kv_lo;
    int P = (kv_lo > 0) ? NPERSIST : 0;
    int tot = cnt + P;

    // stage Q (128 rows x 8 units)
    for (int idx = tid; idx < 1024; idx += 256) {
        int r = idx >> 3, u = idx & 7;
        size_t s = (size_t)(qs + r) * DINNER + h * DH + u * 8;
        int d = r * 128 + ((u ^ (r & 7)) << 4);
        *(float4*)(smem + AQ_H + d) = *(const float4*)(qh_g + s);
        *(float4*)(smem + AQ_L + d) = *(const float4*)(ql_g + s);
    }
    // stage K/V (272 rows, zero-padded beyond tot)
    float4 z = make_float4(0.f, 0.f, 0.f, 0.f);
    for (int idx = tid; idx < 2176; idx += 256) {
        int r = idx >> 3, u = idx & 7;
        int d = r * 128 + ((u ^ (r & 7)) << 4);
        if (r < tot) {
            int gk = (r < cnt) ? (kv_lo + r) : (r - cnt);
            size_t s = (size_t)gk * DINNER + h * DH + u * 8;
            *(float4*)(smem + AK_H + d) = *(const float4*)(kh_g + s);
            *(float4*)(smem + AK_L + d) = *(const float4*)(kl_g + s);
            *(float4*)(smem + AV_H + d) = *(const float4*)(vh_g + s);
            *(float4*)(smem + AV_L + d) = *(const float4*)(vl_g + s);
        } else {
            *(float4*)(smem + AK_H + d) = z;
            *(float4*)(smem + AK_L + d) = z;
            *(float4*)(smem + AV_H + d) = z;
            *(float4*)(smem + AV_L + d) = z;
        }
    }
    __syncthreads();

    // Q fragments (persistent per warp)
    uint32_t qfh[4][4], qfl[4][4];
    {
        int row = warp * 16 + (lane & 15);
#pragma unroll
        for (int ks = 0; ks < 4; ks++) {
            uint32_t a = sb + AQ_H + row * 128 + (((2 * ks + (lane >> 4)) ^ (row & 7)) << 4);
            ldm_x4(qfh[ks][0], qfh[ks][1], qfh[ks][2], qfh[ks][3], a);
            ldm_x4(qfl[ks][0], qfl[ks][1], qfl[ks][2], qfl[ks][3], a + 16384);
        }
    }

    float oacc[8][4];
#pragma unroll
    for (int i = 0; i < 8; i++)
#pragma unroll
        for (int j = 0; j < 4; j++) oacc[i][j] = 0.f;

    float m0 = NEGINF, m1 = NEGINF, l0 = 0.f, l1 = 0.f;
    int rowq0 = qs + warp * 16 + (lane >> 2);
    int rowq1 = rowq0 + 8;
    int pbase = AP + warp * 4096;

    auto process = [&](int row_base, auto NTC) {
        constexpr int NT = decltype(NTC)::value;   // 8 (full) or 2 (mini)
        constexpr int NP = NT / 2;                 // 16-row key groups
        float sacc[NT][4];
#pragma unroll
        for (int i = 0; i < NT; i++)
#pragma unroll
            for (int j = 0; j < 4; j++) sacc[i][j] = 0.f;

#pragma unroll
        for (int ks = 0; ks < 4; ks++) {
            uint32_t kbh[NT][2], kbl[NT][2];
#pragma unroll
            for (int np = 0; np < NP; np++) {
                int r = row_base + np * 16 + (lane & 15);
                uint32_t a = sb + AK_H + r * 128 + (((2 * ks + (lane >> 4)) ^ (r & 7)) << 4);
                uint32_t t0, t1, t2, t3;
                ldm_x4(t0, t1, t2, t3, a);
                kbh[2 * np][0] = t0; kbh[2 * np][1] = t2;
                kbh[2 * np + 1][0] = t1; kbh[2 * np + 1][1] = t3;
                ldm_x4(t0, t1, t2, t3, a + KV_STRIDE);
                kbl[2 * np][0] = t0; kbl[2 * np][1] = t2;
                kbl[2 * np + 1][0] = t1; kbl[2 * np + 1][1] = t3;
            }
#pragma unroll
            for (int nt = 0; nt < NT; nt++) {
                mma_bf16(sacc[nt], qfh[ks], kbh[nt]);
                mma_bf16(sacc[nt], qfh[ks], kbl[nt]);
                mma_bf16(sacc[nt], qfl[ks], kbh[nt]);
            }
        }

        // mask + scale + chunk max
        float cm0 = NEGINF, cm1 = NEGINF;
#pragma unroll
        for (int nt = 0; nt < NT; nt++)
#pragma unroll
            for (int j = 0; j < 4; j++) {
                int key = row_base + nt * 8 + 2 * (lane & 3) + (j & 1);
                int rq = (j < 2) ? rowq0 : rowq1;
                bool ok;
                if (key >= tot) ok = false;
                else if (key < cnt) {
                    int gk = kv_lo + key;
                    ok = (gk <= rq) && ((rq - gk <= WIN) || (gk < NPERSIST));
                } else ok = true;
                float s = ok ? sacc[nt][j] * 0.125f : NEGINF;
                sacc[nt][j] = s;
                if (j < 2) cm0 = fmaxf(cm0, s); else cm1 = fmaxf(cm1, s);
            }
        cm0 = fmaxf(cm0, __shfl_xor_sync(0xffffffffu, cm0, 1));
        cm0 = fmaxf(cm0, __shfl_xor_sync(0xffffffffu, cm0, 2));
        cm1 = fmaxf(cm1, __shfl_xor_sync(0xffffffffu, cm1, 1));
        cm1 = fmaxf(cm1, __shfl_xor_sync(0xffffffffu, cm1, 2));
        float nm0 = fmaxf(m0, cm0), nm1 = fmaxf(m1, cm1);
        float c0 = __expf(m0 - nm0), c1 = __expf(m1 - nm1);
        m0 = nm0; m1 = nm1;

        __syncwarp();
        float sum0 = 0.f, sum1 = 0.f;
        int r0 = lane >> 2, r1 = r0 + 8;
        int ioff = 4 * (lane & 3);
#pragma unroll
        for (int nt = 0; nt < NT; nt++) {
            float p0 = __expf(sacc[nt][0] - m0);
            float p1 = __expf(sacc[nt][1] - m0);
            float p2 = __expf(sacc[nt][2] - m1);
            float p3 = __expf(sacc[nt][3] - m1);
            sum0 += p0 + p1;
            sum1 += p2 + p3;
            int a0 = pbase + r0 * 128 + ((nt ^ (r0 & 7)) << 4) + ioff;
            int a1 = pbase + r1 * 128 + ((nt ^ (r1 & 7)) << 4) + ioff;
            __nv_bfloat16 h0 = __float2bfloat16(p0), h1 = __float2bfloat16(p1);
            __nv_bfloat16 h2 = __float2bfloat16(p2), h3 = __float2bfloat16(p3);
            __nv_bfloat162 w;
            w.x = h0; w.y = h1; *(__nv_bfloat162*)(smem + a0) = w;
            w.x = h2; w.y = h3; *(__nv_bfloat162*)(smem + a1) = w;
            w.x = __float2bfloat16(p0 - __bfloat162float(h0));
            w.y = __float2bfloat16(p1 - __bfloat162float(h1));
            *(__nv_bfloat162*)(smem + a0 + 2048) = w;
            w.x = __float2bfloat16(p2 - __bfloat162float(h2));
            w.y = __float2bfloat16(p3 - __bfloat162float(h3));
            *(__nv_bfloat162*)(smem + a1 + 2048) = w;
        }
        sum0 += __shfl_xor_sync(0xffffffffu, sum0, 1);
        sum0 += __shfl_xor_sync(0xffffffffu, sum0, 2);
        sum1 += __shfl_xor_sync(0xffffffffu, sum1, 1);
        sum1 += __shfl_xor_sync(0xffffffffu, sum1, 2);
        l0 = l0 * c0 + sum0;
        l1 = l1 * c1 + sum1;

#pragma unroll
        for (int dt = 0; dt < 8; dt++) {
            oacc[dt][0] *= c0; oacc[dt][1] *= c0;
            oacc[dt][2] *= c1; oacc[dt][3] *= c1;
        }
        __syncwarp();

        // P*V over NP 16-key steps
#pragma unroll
        for (int kp = 0; kp < NP; kp++) {
            uint32_t pfh[4], pfl[4];
            {
                int row = lane & 15;
                uint32_t a = sb + pbase + row * 128 + (((2 * kp + (lane >> 4)) ^ (row & 7)) << 4);
                ldm_x4(pfh[0], pfh[1], pfh[2], pfh[3], a);
                ldm_x4(pfl[0], pfl[1], pfl[2], pfl[3], a + 2048);
            }
            uint32_t vbh[8][2], vbl[8][2];
#pragma unroll
            for (int np = 0; np < 4; np++) {
                int r = row_base + kp * 16 + (lane & 7) + (((lane >> 4) & 1) << 3);
                int u = np * 2 + ((lane >> 3) & 1);
                uint32_t a = sb + AV_H + r * 128 + ((u ^ (r & 7)) << 4);
                uint32_t t0, t1, t2, t3;
                ldm_x4t(t0, t1, t2, t3, a);
                vbh[2 * np][0] = t0; vbh[2 * np][1] = t2;
                vbh[2 * np + 1][0] = t1; vbh[2 * np + 1][1] = t3;
                ldm_x4t(t0, t1, t2, t3, a + KV_STRIDE);
                vbl[2 * np][0] = t0; vbl[2 * np][1] = t2;
                vbl[2 * np + 1][0] = t1; vbl[2 * np + 1][1] = t3;
            }
#pragma unroll
            for (int dt = 0; dt < 8; dt++) {
                mma_bf16(oacc[dt], pfh, vbh[dt]);
                mma_bf16(oacc[dt], pfh, vbl[dt]);
                mma_bf16(oacc[dt], pfl, vbh[dt]);
            }
        }
        __syncwarp();
    };

    // per-warp chunk bounds
    int rlo = qs + 16 * warp - WIN - kv_lo; if (rlo < 0) rlo = 0;
    int rhi = qs + 16 * warp + 15 - kv_lo;
    int ch_lo = rlo >> 6, ch_hi = rhi >> 6;
    for (int ch = ch_lo; ch <= ch_hi; ch++) process(ch * 64, IC<8>{});
    if (P > 0) process(cnt, IC<2>{});            // persist rows appended at cnt
    else if (ch_lo > 0) process(0, IC<2>{});     // persist keys below chunk range

    float i0 = 1.0f / l0, i1 = 1.0f / l1;
#pragma unroll
    for (int dt = 0; dt < 8; dt++) {
        int col = h * DH + dt * 8 + 2 * (lane & 3);
        split_store(out_hi, out_lo, (size_t)rowq0 * DINNER + col,
                    oacc[dt][0] * i0, oacc[dt][1] * i0);
        split_store(out_hi, out_lo, (size_t)rowq1 * DINNER + col,
                    oacc[dt][2] * i1, oacc[dt][3] * i1);
    }
}

// ---------------------------------------------------------------------------
extern "C" void kernel_launch(void* const* d_in, const int* in_sizes, int n_in,
                              void* d_out, int out_size) {
    const float* seq   = (const float*)d_in[0];
    const float* g     = (const float*)d_in[1];
    const float* w_qkv = (const float*)d_in[2];
    const float* w_out = (const float*)d_in[3];
    float* out = (float*)d_out;

    __nv_bfloat16 *ahi, *alo, *wqh, *wql, *woh, *wol, *athi, *atlo;
    __nv_bfloat16 *qh, *ql, *kh, *kl, *vh, *vl;
    cudaGetSymbolAddress((void**)&ahi, g_a_hi);
    cudaGetSymbolAddress((void**)&alo, g_a_lo);
    cudaGetSymbolAddress((void**)&wqh, g_wqkvT_hi);
    cudaGetSymbolAddress((void**)&wql, g_wqkvT_lo);
    cudaGetSymbolAddress((void**)&woh, g_woutT_hi);
    cudaGetSymbolAddress((void**)&wol, g_woutT_lo);
    cudaGetSymbolAddress((void**)&athi, g_attn_hi);
    cudaGetSymbolAddress((void**)&atlo, g_attn_lo);
    cudaGetSymbolAddress((void**)&qh, g_q_hi);
    cudaGetSymbolAddress((void**)&ql, g_q_lo);
    cudaGetSymbolAddress((void**)&kh, g_k_hi);
    cudaGetSymbolAddress((void**)&kl, g_k_lo);
    cudaGetSymbolAddress((void**)&vh, g_v_hi);
    cudaGetSymbolAddress((void**)&vl, g_v_lo);

    cudaFuncSetAttribute(attn_kernel, cudaFuncAttributeMaxDynamicSharedMemorySize,
                         ATTN_SMEM);
    cudaFuncSetAttribute(gemm_sb16_kernel, cudaFuncAttributeMaxDynamicSharedMemorySize,
                         GEMM_SMEM);

    rope_table_kernel<<<(N_SEQ * 32 + 255) / 256, 256>>>();
    rmsnorm_cvt_kernel<<<N_SEQ, 256>>>(seq, g, ahi, alo);
    transpose_cvt_kernel<<<dim3(QKVC / 32, DMODEL / 32), dim3(32, 8)>>>(
        w_qkv, DMODEL, QKVC, wqh, wql);
    transpose_cvt_kernel<<<dim3(DMODEL / 32, DINNER / 32), dim3(32, 8)>>>(
        w_out, DINNER, DMODEL, woh, wol);

    gemm_sb16_kernel<<<dim3(QKVC / 128, N_SEQ / 128), 256, GEMM_SMEM>>>(
        ahi, alo, wqh, wql, nullptr, DMODEL, QKVC, qh, ql, kh, kl, vh, vl);

    attn_kernel<<<dim3(N_SEQ / 128, HEADS), 256, ATTN_SMEM>>>(
        qh, ql, kh, kl, vh, vl, athi, atlo);

    gemm_sb16_kernel<<<dim3(DMODEL / 128, N_SEQ / 128), 256, GEMM_SMEM>>>(
        athi, atlo, woh, wol, out, DINNER, DMODEL,
        nullptr, nullptr, nullptr, nullptr, nullptr, nullptr);
}

// round 14
// speedup vs baseline: 1.5857x; 1.2861x over previous
#include <cuda_runtime.h>
#include <cuda_bf16.h>
#include <cuda_fp16.h>
#include <math.h>
#include <stdint.h>

#define N_SEQ   4096
#define DMODEL  1024
#define HEADS   8
#define DH      64
#define DINNER  512
#define QKVC    1536
#define WIN     128
#define NPERSIST 4

// ---------------- scratch (device globals; allocation-free rule) ------------
__device__ float2 g_rope[N_SEQ * 32];
__device__ __half g_a_h[N_SEQ * DMODEL];
__device__ __half g_wqkvT_h[QKVC * DMODEL];
__device__ __half g_wqkvT_l[QKVC * DMODEL];
__device__ __half g_woutT_h[DMODEL * DINNER];
__device__ __half g_woutT_l[DMODEL * DINNER];
__device__ __nv_bfloat16 g_q_hi[N_SEQ * DINNER];
__device__ __nv_bfloat16 g_q_lo[N_SEQ * DINNER];
__device__ __nv_bfloat16 g_k_hi[N_SEQ * DINNER];
__device__ __nv_bfloat16 g_k_lo[N_SEQ * DINNER];
__device__ __nv_bfloat16 g_v_hi[N_SEQ * DINNER];
__device__ __nv_bfloat16 g_v_lo[N_SEQ * DINNER];
__device__ __half g_attn_h[N_SEQ * DINNER];

template <int N> struct IC { static constexpr int value = N; };

// ---------------- helpers ----------------------------------------------
__device__ __forceinline__ uint32_t smem_u32(const void* p) {
    uint32_t a;
    asm("{ .reg .u64 t; cvta.to.shared.u64 t, %1; cvt.u32.u64 %0, t; }" : "=r"(a) : "l"(p));
    return a;
}
__device__ __forceinline__ void cp_async16(uint32_t dst, const void* src) {
    asm volatile("cp.async.cg.shared.global [%0], [%1], 16;" :: "r"(dst), "l"(src));
}
__device__ __forceinline__ void cp_commit() {
    asm volatile("cp.async.commit_group;" ::: "memory");
}
template <int N>
__device__ __forceinline__ void cp_wait() {
    asm volatile("cp.async.wait_group %0;" :: "n"(N) : "memory");
}
__device__ __forceinline__ void ldm_x4(uint32_t& r0, uint32_t& r1, uint32_t& r2,
                                       uint32_t& r3, uint32_t addr) {
    asm volatile("ldmatrix.sync.aligned.m8n8.x4.shared.b16 {%0,%1,%2,%3}, [%4];"
                 : "=r"(r0), "=r"(r1), "=r"(r2), "=r"(r3) : "r"(addr));
}
__device__ __forceinline__ void ldm_x4t(uint32_t& r0, uint32_t& r1, uint32_t& r2,
                                        uint32_t& r3, uint32_t addr) {
    asm volatile("ldmatrix.sync.aligned.m8n8.x4.trans.shared.b16 {%0,%1,%2,%3}, [%4];"
                 : "=r"(r0), "=r"(r1), "=r"(r2), "=r"(r3) : "r"(addr));
}
__device__ __forceinline__ void mma_bf16(float* d, const uint32_t* a, const uint32_t* b) {
    asm volatile("mma.sync.aligned.m16n8k16.row.col.f32.bf16.bf16.f32 "
                 "{%0,%1,%2,%3}, {%4,%5,%6,%7}, {%8,%9}, {%0,%1,%2,%3};"
                 : "+f"(d[0]), "+f"(d[1]), "+f"(d[2]), "+f"(d[3])
                 : "r"(a[0]), "r"(a[1]), "r"(a[2]), "r"(a[3]), "r"(b[0]), "r"(b[1]));
}
__device__ __forceinline__ void mma_f16(float* d, const uint32_t* a, const uint32_t* b) {
    asm volatile("mma.sync.aligned.m16n8k16.row.col.f32.f16.f16.f32 "
                 "{%0,%1,%2,%3}, {%4,%5,%6,%7}, {%8,%9}, {%0,%1,%2,%3};"
                 : "+f"(d[0]), "+f"(d[1]), "+f"(d[2]), "+f"(d[3])
                 : "r"(a[0]), "r"(a[1]), "r"(a[2]), "r"(a[3]), "r"(b[0]), "r"(b[1]));
}
__device__ __forceinline__ void split_store_bf(__nv_bfloat16* hp, __nv_bfloat16* lp,
                                               size_t off, float x, float y) {
    __nv_bfloat16 hx = __float2bfloat16(x), hy = __float2bfloat16(y);
    __nv_bfloat162 w;
    w.x = hx; w.y = hy;
    *(__nv_bfloat162*)(hp + off) = w;
    w.x = __float2bfloat16(x - __bfloat162float(hx));
    w.y = __float2bfloat16(y - __bfloat162float(hy));
    *(__nv_bfloat162*)(lp + off) = w;
}

// ---------------------------------------------------------------------------
// RoPE table
// ---------------------------------------------------------------------------
__global__ void rope_table_kernel() {
    int idx = blockIdx.x * blockDim.x + threadIdx.x;
    if (idx >= N_SEQ * 32) return;
    int n = idx >> 5;
    int t = idx & 31;
    float inv = (float)exp(-(double)t * (9.210340371976184 / 32.0));
    float s, c;
    sincosf((float)n * inv, &s, &c);
    g_rope[idx] = make_float2(c, s);
}

// ---------------------------------------------------------------------------
// RMSNorm -> fp16 (single plane)
// ---------------------------------------------------------------------------
__global__ void rmsnorm_cvt_kernel(const float* __restrict__ seq,
                                   const float* __restrict__ g,
                                   __half* __restrict__ out) {
    int row = blockIdx.x;
    int t = threadIdx.x;
    float4 v = ((const float4*)(seq + row * DMODEL))[t];
    float ss = v.x * v.x + v.y * v.y + v.z * v.z + v.w * v.w;
#pragma unroll
    for (int o = 16; o > 0; o >>= 1) ss += __shfl_xor_sync(0xffffffffu, ss, o);
    __shared__ float ws[8];
    if ((t & 31) == 0) ws[t >> 5] = ss;
    __syncthreads();
    float tot = ws[0] + ws[1] + ws[2] + ws[3] + ws[4] + ws[5] + ws[6] + ws[7];
    float inv = rsqrtf(tot * (1.0f / (float)DMODEL) + 1.1920929e-07f);
    float4 gv = ((const float4*)g)[t];
    size_t base = (size_t)row * DMODEL + t * 4;
    __half2 w;
    w.x = __float2half(v.x * inv * gv.x);
    w.y = __float2half(v.y * inv * gv.y);
    *(__half2*)(out + base) = w;
    w.x = __float2half(v.z * inv * gv.z);
    w.y = __float2half(v.w * inv * gv.w);
    *(__half2*)(out + base + 2) = w;
}

// ---------------------------------------------------------------------------
// Transpose + fp16 hi/lo split: src[K][N] -> dst[N][K]
// ---------------------------------------------------------------------------
__global__ void transpose_cvt_kernel(const float* __restrict__ src, int K, int N,
                                     __half* __restrict__ hi,
                                     __half* __restrict__ lo) {
    __shared__ float tile[32][33];
    int bx = blockIdx.x, by = blockIdx.y;
    int tx = threadIdx.x, ty = threadIdx.y;
#pragma unroll
    for (int i = 0; i < 4; i++) {
        int k = by * 32 + ty + 8 * i;
        int n = bx * 32 + tx;
        tile[ty + 8 * i][tx] = src[(size_t)k * N + n];
    }
    __syncthreads();
#pragma unroll
    for (int i = 0; i < 4; i++) {
        int n = bx * 32 + ty + 8 * i;
        int k = by * 32 + tx;
        float v = tile[tx][ty + 8 * i];
        __half h = __float2half(v);
        hi[(size_t)n * K + k] = h;
        lo[(size_t)n * K + k] = __float2half(v - __half2float(h));
    }
}

// ---------------------------------------------------------------------------
// fp16 2-term GEMM via mma.sync: C = A * (Bh+Bl)^T, A single fp16 plane.
// qkv mode (qh != nullptr): fused table RoPE + split to bf16 q/k/v planes.
// ---------------------------------------------------------------------------
#define GEMM_SMEM (2 * 3 * 16384)

struct Frag {
    uint32_t ah[4][4], bh[4][2], bl[4][2];
};

__global__ __launch_bounds__(256, 1)
void gemm_f16_kernel(const __half* __restrict__ A,
                     const __half* __restrict__ Bh,
                     const __half* __restrict__ Bl,
                     float* __restrict__ C, int K, int ldc,
                     __nv_bfloat16* qh, __nv_bfloat16* ql,
                     __nv_bfloat16* kh, __nv_bfloat16* kl,
                     __nv_bfloat16* vh, __nv_bfloat16* vl) {
    extern __shared__ char smem[];
    uint32_t sb = smem_u32(smem);
    int tid = threadIdx.x;
    int wid = tid >> 5, lane = tid & 31;
    int m0 = blockIdx.y * 128, n0 = blockIdx.x * 128;
    int wm = wid & 1;
    int wn = wid >> 1;

    auto prefetch = [&](int c, int buf) {
        int kc = c << 6;
        uint32_t b32 = sb + buf * 49152;
#pragma unroll
        for (int i = 0; i < 4; i++) {
            int idx = tid + 256 * i;
            int r = idx >> 3, u = idx & 7;
            uint32_t dst = b32 + r * 128 + ((u ^ (r & 7)) << 4);
            size_t ga = (size_t)(m0 + r) * K + kc + u * 8;
            size_t gb = (size_t)(n0 + r) * K + kc + u * 8;
            cp_async16(dst,         A + ga);
            cp_async16(dst + 16384, Bh + gb);
            cp_async16(dst + 32768, Bl + gb);
        }
        cp_commit();
    };

    auto load_frags = [&](uint32_t b32, int ks, Frag& f) {
#pragma unroll
        for (int mt = 0; mt < 4; mt++) {
            int r = wm * 64 + mt * 16 + (lane & 15);
            int u = 2 * ks + (lane >> 4);
            uint32_t addr = b32 + r * 128 + ((u ^ (r & 7)) << 4);
            ldm_x4(f.ah[mt][0], f.ah[mt][1], f.ah[mt][2], f.ah[mt][3], addr);
        }
#pragma unroll
        for (int np = 0; np < 2; np++) {
            int r = wn * 32 + np * 16 + (lane & 15);
            int u = 2 * ks + (lane >> 4);
            uint32_t addr = b32 + 16384 + r * 128 + ((u ^ (r & 7)) << 4);
            uint32_t t0, t1, t2, t3;
            ldm_x4(t0, t1, t2, t3, addr);
            f.bh[2 * np][0] = t0; f.bh[2 * np][1] = t2;
            f.bh[2 * np + 1][0] = t1; f.bh[2 * np + 1][1] = t3;
            ldm_x4(t0, t1, t2, t3, addr + 16384);
            f.bl[2 * np][0] = t0; f.bl[2 * np][1] = t2;
            f.bl[2 * np + 1][0] = t1; f.bl[2 * np + 1][1] = t3;
        }
    };

    float acc[4][4][4];
#pragma unroll
    for (int i = 0; i < 4; i++)
#pragma unroll
        for (int j = 0; j < 4; j++)
#pragma unroll
            for (int k = 0; k < 4; k++) acc[i][j][k] = 0.f;

    int NC = K >> 6;
    prefetch(0, 0);

    Frag f0, f1;
    for (int c = 0; c < NC; c++) {
        int buf = c & 1;
        if (c + 1 < NC) {
            prefetch(c + 1, buf ^ 1);
            cp_wait<1>();
        } else {
            cp_wait<0>();
        }
        __syncthreads();

        uint32_t b32 = sb + buf * 49152;
        load_frags(b32, 0, f0);
#pragma unroll
        for (int ks = 0; ks < 4; ks++) {
            Frag& cur = (ks & 1) ? f1 : f0;
            Frag& nxt = (ks & 1) ? f0 : f1;
            if (ks < 3) load_frags(b32, ks + 1, nxt);
#pragma unroll
            for (int mt = 0; mt < 4; mt++)
#pragma unroll
                for (int nt = 0; nt < 4; nt++) {
                    mma_f16(acc[mt][nt], cur.ah[mt], cur.bh[nt]);
                    mma_f16(acc[mt][nt], cur.ah[mt], cur.bl[nt]);
                }
        }
        __syncthreads();
    }

    int rbase = m0 + wm * 64 + (lane >> 2);
    int cbase = n0 + wn * 32 + (lane & 3) * 2;
    bool qkv_mode = (qh != nullptr);

#pragma unroll
    for (int mt = 0; mt < 4; mt++)
#pragma unroll
        for (int nt = 0; nt < 4; nt++) {
            int row = rbase + mt * 16;
            int col = cbase + nt * 8;
            float2 v0 = make_float2(acc[mt][nt][0], acc[mt][nt][1]);
            float2 v1 = make_float2(acc[mt][nt][2], acc[mt][nt][3]);
            if (qkv_mode) {
                if (col < 2 * DINNER) {
                    int t = (col & 63) >> 1;
                    float2 cs0 = g_rope[row * 32 + t];
                    float2 cs1 = g_rope[(row + 8) * 32 + t];
                    float a = v0.x, b = v0.y;
                    v0.x = a * cs0.x - b * cs0.y;
                    v0.y = b * cs0.x + a * cs0.y;
                    a = v1.x; b = v1.y;
                    v1.x = a * cs1.x - b * cs1.y;
                    v1.y = b * cs1.x + a * cs1.y;
                }
                int sec = col >> 9;
                __nv_bfloat16 *hp, *lp;
                if (sec == 0) { hp = qh; lp = ql; }
                else if (sec == 1) { hp = kh; lp = kl; }
                else { hp = vh; lp = vl; }
                int cc = col & 511;
                split_store_bf(hp, lp, (size_t)row * DINNER + cc, v0.x, v0.y);
                split_store_bf(hp, lp, (size_t)(row + 8) * DINNER + cc, v1.x, v1.y);
            } else {
                *(float2*)(C + (size_t)row * ldc + col) = v0;
                *(float2*)(C + (size_t)(row + 8) * ldc + col) = v1;
            }
        }
}

// ---------------------------------------------------------------------------
// Tensor-core attention (R13): 128 queries/block, 8 warps x 16 queries,
// per-warp chunk bounds + persist mini chunk. Output: fp16 single plane.
// ---------------------------------------------------------------------------
#define AQ_H 0
#define AQ_L 16384
#define AK_H 32768
#define KV_STRIDE (272 * 128)
#define AK_L (AK_H + KV_STRIDE)
#define AV_H (AK_L + KV_STRIDE)
#define AV_L (AV_H + KV_STRIDE)
#define AP   (AV_L + KV_STRIDE)
#define ATTN_SMEM (AP + 8 * 4096)
#define NEGINF (-1e30f)

__global__ __launch_bounds__(256) void attn_kernel(
    const __nv_bfloat16* __restrict__ qh_g, const __nv_bfloat16* __restrict__ ql_g,
    const __nv_bfloat16* __restrict__ kh_g, const __nv_bfloat16* __restrict__ kl_g,
    const __nv_bfloat16* __restrict__ vh_g, const __nv_bfloat16* __restrict__ vl_g,
    __half* __restrict__ out_h) {
    extern __shared__ char smem[];
    uint32_t sb = smem_u32(smem);
    int h = blockIdx.y;
    int qs = blockIdx.x * 128;
    int tid = threadIdx.x;
    int warp = tid >> 5, lane = tid & 31;

    int kv_lo = qs - WIN; if (kv_lo < 0) kv_lo = 0;
    int cnt = qs + 128 - kv_lo;
    int P = (kv_lo > 0) ? NPERSIST : 0;
    int tot = cnt + P;

    for (int idx = tid; idx < 1024; idx += 256) {
        int r = idx >> 3, u = idx & 7;
        size_t s = (size_t)(qs + r) * DINNER + h * DH + u * 8;
        int d = r * 128 + ((u ^ (r & 7)) << 4);
        *(float4*)(smem + AQ_H + d) = *(const float4*)(qh_g + s);
        *(float4*)(smem + AQ_L + d) = *(const float4*)(ql_g + s);
    }
    float4 z = make_float4(0.f, 0.f, 0.f, 0.f);
    for (int idx = tid; idx < 2176; idx += 256) {
        int r = idx >> 3, u = idx & 7;
        int d = r * 128 + ((u ^ (r & 7)) << 4);
        if (r < tot) {
            int gk = (r < cnt) ? (kv_lo + r) : (r - cnt);
            size_t s = (size_t)gk * DINNER + h * DH + u * 8;
            *(float4*)(smem + AK_H + d) = *(const float4*)(kh_g + s);
            *(float4*)(smem + AK_L + d) = *(const float4*)(kl_g + s);
            *(float4*)(smem + AV_H + d) = *(const float4*)(vh_g + s);
            *(float4*)(smem + AV_L + d) = *(const float4*)(vl_g + s);
        } else {
            *(float4*)(smem + AK_H + d) = z;
            *(float4*)(smem + AK_L + d) = z;
            *(float4*)(smem + AV_H + d) = z;
            *(float4*)(smem + AV_L + d) = z;
        }
    }
    __syncthreads();

    uint32_t qfh[4][4], qfl[4][4];
    {
        int row = warp * 16 + (lane & 15);
#pragma unroll
        for (int ks = 0; ks < 4; ks++) {
            uint32_t a = sb + AQ_H + row * 128 + (((2 * ks + (lane >> 4)) ^ (row & 7)) << 4);
            ldm_x4(qfh[ks][0], qfh[ks][1], qfh[ks][2], qfh[ks][3], a);
            ldm_x4(qfl[ks][0], qfl[ks][1], qfl[ks][2], qfl[ks][3], a + 16384);
        }
    }

    float oacc[8][4];
#pragma unroll
    for (int i = 0; i < 8; i++)
#pragma unroll
        for (int j = 0; j < 4; j++) oacc[i][j] = 0.f;

    float m0 = NEGINF, m1 = NEGINF, l0 = 0.f, l1 = 0.f;
    int rowq0 = qs + warp * 16 + (lane >> 2);
    int rowq1 = rowq0 + 8;
    int pbase = AP + warp * 4096;

    auto process = [&](int row_base, auto NTC) {
        constexpr int NT = decltype(NTC)::value;
        constexpr int NP = NT / 2;
        float sacc[NT][4];
#pragma unroll
        for (int i = 0; i < NT; i++)
#pragma unroll
            for (int j = 0; j < 4; j++) sacc[i][j] = 0.f;

#pragma unroll
        for (int ks = 0; ks < 4; ks++) {
            uint32_t kbh[NT][2], kbl[NT][2];
#pragma unroll
            for (int np = 0; np < NP; np++) {
                int r = row_base + np * 16 + (lane & 15);
                uint32_t a = sb + AK_H + r * 128 + (((2 * ks + (lane >> 4)) ^ (r & 7)) << 4);
                uint32_t t0, t1, t2, t3;
                ldm_x4(t0, t1, t2, t3, a);
                kbh[2 * np][0] = t0; kbh[2 * np][1] = t2;
                kbh[2 * np + 1][0] = t1; kbh[2 * np + 1][1] = t3;
                ldm_x4(t0, t1, t2, t3, a + KV_STRIDE);
                kbl[2 * np][0] = t0; kbl[2 * np][1] = t2;
                kbl[2 * np + 1][0] = t1; kbl[2 * np + 1][1] = t3;
            }
#pragma unroll
            for (int nt = 0; nt < NT; nt++) {
                mma_bf16(sacc[nt], qfh[ks], kbh[nt]);
                mma_bf16(sacc[nt], qfh[ks], kbl[nt]);
                mma_bf16(sacc[nt], qfl[ks], kbh[nt]);
            }
        }

        float cm0 = NEGINF, cm1 = NEGINF;
#pragma unroll
        for (int nt = 0; nt < NT; nt++)
#pragma unroll
            for (int j = 0; j < 4; j++) {
                int key = row_base + nt * 8 + 2 * (lane & 3) + (j & 1);
                int rq = (j < 2) ? rowq0 : rowq1;
                bool ok;
                if (key >= tot) ok = false;
                else if (key < cnt) {
                    int gk = kv_lo + key;
                    ok = (gk <= rq) && ((rq - gk <= WIN) || (gk < NPERSIST));
                } else ok = true;
                float s = ok ? sacc[nt][j] * 0.125f : NEGINF;
                sacc[nt][j] = s;
                if (j < 2) cm0 = fmaxf(cm0, s); else cm1 = fmaxf(cm1, s);
            }
        cm0 = fmaxf(cm0, __shfl_xor_sync(0xffffffffu, cm0, 1));
        cm0 = fmaxf(cm0, __shfl_xor_sync(0xffffffffu, cm0, 2));
        cm1 = fmaxf(cm1, __shfl_xor_sync(0xffffffffu, cm1, 1));
        cm1 = fmaxf(cm1, __shfl_xor_sync(0xffffffffu, cm1, 2));
        float nm0 = fmaxf(m0, cm0), nm1 = fmaxf(m1, cm1);
        float c0 = __expf(m0 - nm0), c1 = __expf(m1 - nm1);
        m0 = nm0; m1 = nm1;

        __syncwarp();
        float sum0 = 0.f, sum1 = 0.f;
        int r0 = lane >> 2, r1 = r0 + 8;
        int ioff = 4 * (lane & 3);
#pragma unroll
        for (int nt = 0; nt < NT; nt++) {
            float p0 = __expf(sacc[nt][0] - m0);
            float p1 = __expf(sacc[nt][1] - m0);
            float p2 = __expf(sacc[nt][2] - m1);
            float p3 = __expf(sacc[nt][3] - m1);
            sum0 += p0 + p1;
            sum1 += p2 + p3;
            int a0 = pbase + r0 * 128 + ((nt ^ (r0 & 7)) << 4) + ioff;
            int a1 = pbase + r1 * 128 + ((nt ^ (r1 & 7)) << 4) + ioff;
            __nv_bfloat16 h0 = __float2bfloat16(p0), h1 = __float2bfloat16(p1);
            __nv_bfloat16 h2 = __float2bfloat16(p2), h3 = __float2bfloat16(p3);
            __nv_bfloat162 w;
            w.x = h0; w.y = h1; *(__nv_bfloat162*)(smem + a0) = w;
            w.x = h2; w.y = h3; *(__nv_bfloat162*)(smem + a1) = w;
            w.x = __float2bfloat16(p0 - __bfloat162float(h0));
            w.y = __float2bfloat16(p1 - __bfloat162float(h1));
            *(__nv_bfloat162*)(smem + a0 + 2048) = w;
            w.x = __float2bfloat16(p2 - __bfloat162float(h2));
            w.y = __float2bfloat16(p3 - __bfloat162float(h3));
            *(__nv_bfloat162*)(smem + a1 + 2048) = w;
        }
        sum0 += __shfl_xor_sync(0xffffffffu, sum0, 1);
        sum0 += __shfl_xor_sync(0xffffffffu, sum0, 2);
        sum1 += __shfl_xor_sync(0xffffffffu, sum1, 1);
        sum1 += __shfl_xor_sync(0xffffffffu, sum1, 2);
        l0 = l0 * c0 + sum0;
        l1 = l1 * c1 + sum1;

#pragma unroll
        for (int dt = 0; dt < 8; dt++) {
            oacc[dt][0] *= c0; oacc[dt][1] *= c0;
            oacc[dt][2] *= c1; oacc[dt][3] *= c1;
        }
        __syncwarp();

#pragma unroll
        for (int kp = 0; kp < NP; kp++) {
            uint32_t pfh[4], pfl[4];
            {
                int row = lane & 15;
                uint32_t a = sb + pbase + row * 128 + (((2 * kp + (lane >> 4)) ^ (row & 7)) << 4);
                ldm_x4(pfh[0], pfh[1], pfh[2], pfh[3], a);
                ldm_x4(pfl[0], pfl[1], pfl[2], pfl[3], a + 2048);
            }
            uint32_t vbh[8][2], vbl[8][2];
#pragma unroll
            for (int np = 0; np < 4; np++) {
                int r = row_base + kp * 16 + (lane & 7) + (((lane >> 4) & 1) << 3);
                int u = np * 2 + ((lane >> 3) & 1);
                uint32_t a = sb + AV_H + r * 128 + ((u ^ (r & 7)) << 4);
                uint32_t t0, t1, t2, t3;
                ldm_x4t(t0, t1, t2, t3, a);
                vbh[2 * np][0] = t0; vbh[2 * np][1] = t2;
                vbh[2 * np + 1][0] = t1; vbh[2 * np + 1][1] = t3;
                ldm_x4t(t0, t1, t2, t3, a + KV_STRIDE);
                vbl[2 * np][0] = t0; vbl[2 * np][1] = t2;
                vbl[2 * np + 1][0] = t1; vbl[2 * np + 1][1] = t3;
            }
#pragma unroll
            for (int dt = 0; dt < 8; dt++) {
                mma_bf16(oacc[dt], pfh, vbh[dt]);
                mma_bf16(oacc[dt], pfh, vbl[dt]);
                mma_bf16(oacc[dt], pfl, vbh[dt]);
            }
        }
        __syncwarp();
    };

    int rlo = qs + 16 * warp - WIN - kv_lo; if (rlo < 0) rlo = 0;
    int rhi = qs + 16 * warp + 15 - kv_lo;
    int ch_lo = rlo >> 6, ch_hi = rhi >> 6;
    for (int ch = ch_lo; ch <= ch_hi; ch++) process(ch * 64, IC<8>{});
    if (P > 0) process(cnt, IC<2>{});
    else if (ch_lo > 0) process(0, IC<2>{});

    float i0 = 1.0f / l0, i1 = 1.0f / l1;
#pragma unroll
    for (int dt = 0; dt < 8; dt++) {
        int col = h * DH + dt * 8 + 2 * (lane & 3);
        __half2 w;
        w.x = __float2half(oacc[dt][0] * i0);
        w.y = __float2half(oacc[dt][1] * i0);
        *(__half2*)(out_h + (size_t)rowq0 * DINNER + col) = w;
        w.x = __float2half(oacc[dt][2] * i1);
        w.y = __float2half(oacc[dt][3] * i1);
        *(__half2*)(out_h + (size_t)rowq1 * DINNER + col) = w;
    }
}

// ---------------------------------------------------------------------------
extern "C" void kernel_launch(void* const* d_in, const int* in_sizes, int n_in,
                              void* d_out, int out_size) {
    const float* seq   = (const float*)d_in[0];
    const float* g     = (const float*)d_in[1];
    const float* w_qkv = (const float*)d_in[2];
    const float* w_out = (const float*)d_in[3];
    float* out = (float*)d_out;

    __half *ah, *wqh, *wql, *woh, *wol, *ath;
    __nv_bfloat16 *qh, *ql, *kh, *kl, *vh, *vl;
    cudaGetSymbolAddress((void**)&ah, g_a_h);
    cudaGetSymbolAddress((void**)&wqh, g_wqkvT_h);
    cudaGetSymbolAddress((void**)&wql, g_wqkvT_l);
    cudaGetSymbolAddress((void**)&woh, g_woutT_h);
    cudaGetSymbolAddress((void**)&wol, g_woutT_l);
    cudaGetSymbolAddress((void**)&ath, g_attn_h);
    cudaGetSymbolAddress((void**)&qh, g_q_hi);
    cudaGetSymbolAddress((void**)&ql, g_q_lo);
    cudaGetSymbolAddress((void**)&kh, g_k_hi);
    cudaGetSymbolAddress((void**)&kl, g_k_lo);
    cudaGetSymbolAddress((void**)&vh, g_v_hi);
    cudaGetSymbolAddress((void**)&vl, g_v_lo);

    cudaFuncSetAttribute(attn_kernel, cudaFuncAttributeMaxDynamicSharedMemorySize,
                         ATTN_SMEM);
    cudaFuncSetAttribute(gemm_f16_kernel, cudaFuncAttributeMaxDynamicSharedMemorySize,
                         GEMM_SMEM);

    rope_table_kernel<<<(N_SEQ * 32 + 255) / 256, 256>>>();
    rmsnorm_cvt_kernel<<<N_SEQ, 256>>>(seq, g, ah);
    transpose_cvt_kernel<<<dim3(QKVC / 32, DMODEL / 32), dim3(32, 8)>>>(
        w_qkv, DMODEL, QKVC, wqh, wql);
    transpose_cvt_kernel<<<dim3(DMODEL / 32, DINNER / 32), dim3(32, 8)>>>(
        w_out, DINNER, DMODEL, woh, wol);

    gemm_f16_kernel<<<dim3(QKVC / 128, N_SEQ / 128), 256, GEMM_SMEM>>>(
        ah, wqh, wql, nullptr, DMODEL, QKVC, qh, ql, kh, kl, vh, vl);

    attn_kernel<<<dim3(N_SEQ / 128, HEADS), 256, ATTN_SMEM>>>(
        qh, ql, kh, kl, vh, vl, ath);

    gemm_f16_kernel<<<dim3(DMODEL / 128, N_SEQ / 128), 256, GEMM_SMEM>>>(
        ath, woh, wol, out, DINNER, DMODEL,
        nullptr, nullptr, nullptr, nullptr, nullptr, nullptr);
}

// round 16
// speedup vs baseline: 2.2929x; 1.4460x over previous
#include <cuda_runtime.h>
#include <cuda_bf16.h>
#include <cuda_fp16.h>
#include <math.h>
#include <stdint.h>

#define N_SEQ   4096
#define DMODEL  1024
#define HEADS   8
#define DH      64
#define DINNER  512
#define QKVC    1536
#define WIN     128
#define NPERSIST 4

// ---------------- scratch (device globals; allocation-free rule) ------------
__device__ float2 g_rope[N_SEQ * 32];
__device__ __half g_a_h[N_SEQ * DMODEL];
__device__ __half g_wqkvT_h[QKVC * DMODEL];
__device__ __half g_woutT_h[DMODEL * DINNER];
__device__ __nv_bfloat16 g_q_hi[N_SEQ * DINNER];
__device__ __nv_bfloat16 g_q_lo[N_SEQ * DINNER];
__device__ __nv_bfloat16 g_k_hi[N_SEQ * DINNER];
__device__ __nv_bfloat16 g_k_lo[N_SEQ * DINNER];
__device__ __nv_bfloat16 g_v_hi[N_SEQ * DINNER];
__device__ __nv_bfloat16 g_v_lo[N_SEQ * DINNER];
__device__ __half g_attn_h[N_SEQ * DINNER];

template <int N> struct IC { static constexpr int value = N; };

// ---------------- helpers ----------------------------------------------
__device__ __forceinline__ uint32_t smem_u32(const void* p) {
    uint32_t a;
    asm("{ .reg .u64 t; cvta.to.shared.u64 t, %1; cvt.u32.u64 %0, t; }" : "=r"(a) : "l"(p));
    return a;
}
__device__ __forceinline__ void cp_async16(uint32_t dst, const void* src) {
    asm volatile("cp.async.cg.shared.global [%0], [%1], 16;" :: "r"(dst), "l"(src));
}
__device__ __forceinline__ void cp_commit() {
    asm volatile("cp.async.commit_group;" ::: "memory");
}
template <int N>
__device__ __forceinline__ void cp_wait() {
    asm volatile("cp.async.wait_group %0;" :: "n"(N) : "memory");
}
__device__ __forceinline__ void ldm_x4(uint32_t& r0, uint32_t& r1, uint32_t& r2,
                                       uint32_t& r3, uint32_t addr) {
    asm volatile("ldmatrix.sync.aligned.m8n8.x4.shared.b16 {%0,%1,%2,%3}, [%4];"
                 : "=r"(r0), "=r"(r1), "=r"(r2), "=r"(r3) : "r"(addr));
}
__device__ __forceinline__ void ldm_x4t(uint32_t& r0, uint32_t& r1, uint32_t& r2,
                                        uint32_t& r3, uint32_t addr) {
    asm volatile("ldmatrix.sync.aligned.m8n8.x4.trans.shared.b16 {%0,%1,%2,%3}, [%4];"
                 : "=r"(r0), "=r"(r1), "=r"(r2), "=r"(r3) : "r"(addr));
}
__device__ __forceinline__ void mma_bf16(float* d, const uint32_t* a, const uint32_t* b) {
    asm volatile("mma.sync.aligned.m16n8k16.row.col.f32.bf16.bf16.f32 "
                 "{%0,%1,%2,%3}, {%4,%5,%6,%7}, {%8,%9}, {%0,%1,%2,%3};"
                 : "+f"(d[0]), "+f"(d[1]), "+f"(d[2]), "+f"(d[3])
                 : "r"(a[0]), "r"(a[1]), "r"(a[2]), "r"(a[3]), "r"(b[0]), "r"(b[1]));
}
__device__ __forceinline__ void mma_f16(float* d, const uint32_t* a, const uint32_t* b) {
    asm volatile("mma.sync.aligned.m16n8k16.row.col.f32.f16.f16.f32 "
                 "{%0,%1,%2,%3}, {%4,%5,%6,%7}, {%8,%9}, {%0,%1,%2,%3};"
                 : "+f"(d[0]), "+f"(d[1]), "+f"(d[2]), "+f"(d[3])
                 : "r"(a[0]), "r"(a[1]), "r"(a[2]), "r"(a[3]), "r"(b[0]), "r"(b[1]));
}
__device__ __forceinline__ void split_store_bf(__nv_bfloat16* hp, __nv_bfloat16* lp,
                                               size_t off, float x, float y) {
    __nv_bfloat16 hx = __float2bfloat16(x), hy = __float2bfloat16(y);
    __nv_bfloat162 w;
    w.x = hx; w.y = hy;
    *(__nv_bfloat162*)(hp + off) = w;
    w.x = __float2bfloat16(x - __bfloat162float(hx));
    w.y = __float2bfloat16(y - __bfloat162float(hy));
    *(__nv_bfloat162*)(lp + off) = w;
}

// ---------------------------------------------------------------------------
// RoPE table
// ---------------------------------------------------------------------------
__global__ void rope_table_kernel() {
    int idx = blockIdx.x * blockDim.x + threadIdx.x;
    if (idx >= N_SEQ * 32) return;
    int n = idx >> 5;
    int t = idx & 31;
    float inv = (float)exp(-(double)t * (9.210340371976184 / 32.0));
    float s, c;
    sincosf((float)n * inv, &s, &c);
    g_rope[idx] = make_float2(c, s);
}

// ---------------------------------------------------------------------------
// RMSNorm -> fp16 (single plane)
// ---------------------------------------------------------------------------
__global__ void rmsnorm_cvt_kernel(const float* __restrict__ seq,
                                   const float* __restrict__ g,
                                   __half* __restrict__ out) {
    int row = blockIdx.x;
    int t = threadIdx.x;
    float4 v = ((const float4*)(seq + row * DMODEL))[t];
    float ss = v.x * v.x + v.y * v.y + v.z * v.z + v.w * v.w;
#pragma unroll
    for (int o = 16; o > 0; o >>= 1) ss += __shfl_xor_sync(0xffffffffu, ss, o);
    __shared__ float ws[8];
    if ((t & 31) == 0) ws[t >> 5] = ss;
    __syncthreads();
    float tot = ws[0] + ws[1] + ws[2] + ws[3] + ws[4] + ws[5] + ws[6] + ws[7];
    float inv = rsqrtf(tot * (1.0f / (float)DMODEL) + 1.1920929e-07f);
    float4 gv = ((const float4*)g)[t];
    size_t base = (size_t)row * DMODEL + t * 4;
    __half2 w;
    w.x = __float2half(v.x * inv * gv.x);
    w.y = __float2half(v.y * inv * gv.y);
    *(__half2*)(out + base) = w;
    w.x = __float2half(v.z * inv * gv.z);
    w.y = __float2half(v.w * inv * gv.w);
    *(__half2*)(out + base + 2) = w;
}

// ---------------------------------------------------------------------------
// Transpose + fp16 convert: src[K][N] -> dst[N][K] (single plane)
// ---------------------------------------------------------------------------
__global__ void transpose_cvt_kernel(const float* __restrict__ src, int K, int N,
                                     __half* __restrict__ dst) {
    __shared__ float tile[32][33];
    int bx = blockIdx.x, by = blockIdx.y;
    int tx = threadIdx.x, ty = threadIdx.y;
#pragma unroll
    for (int i = 0; i < 4; i++) {
        int k = by * 32 + ty + 8 * i;
        int n = bx * 32 + tx;
        tile[ty + 8 * i][tx] = src[(size_t)k * N + n];
    }
    __syncthreads();
#pragma unroll
    for (int i = 0; i < 4; i++) {
        int n = bx * 32 + ty + 8 * i;
        int k = by * 32 + tx;
        dst[(size_t)n * K + k] = __float2half(tile[tx][ty + 8 * i]);
    }
}

// ---------------------------------------------------------------------------
// Single-plane fp16 GEMM via mma.sync: C = A * B^T.
// qkv mode (qh != nullptr): fused table RoPE + split to bf16 q/k/v planes.
// ---------------------------------------------------------------------------
#define GEMM_SMEM (2 * 2 * 16384)

struct Frag {
    uint32_t ah[4][4], bh[4][2];
};

__global__ __launch_bounds__(256)
void gemm_f16_kernel(const __half* __restrict__ A,
                     const __half* __restrict__ B,
                     float* __restrict__ C, int K, int ldc,
                     __nv_bfloat16* qh, __nv_bfloat16* ql,
                     __nv_bfloat16* kh, __nv_bfloat16* kl,
                     __nv_bfloat16* vh, __nv_bfloat16* vl) {
    extern __shared__ char smem[];
    uint32_t sb = smem_u32(smem);
    int tid = threadIdx.x;
    int wid = tid >> 5, lane = tid & 31;
    int m0 = blockIdx.y * 128, n0 = blockIdx.x * 128;
    int wm = wid & 1;
    int wn = wid >> 1;

    auto prefetch = [&](int c, int buf) {
        int kc = c << 6;
        uint32_t b32 = sb + buf * 32768;
#pragma unroll
        for (int i = 0; i < 4; i++) {
            int idx = tid + 256 * i;
            int r = idx >> 3, u = idx & 7;
            uint32_t dst = b32 + r * 128 + ((u ^ (r & 7)) << 4);
            size_t ga = (size_t)(m0 + r) * K + kc + u * 8;
            size_t gb = (size_t)(n0 + r) * K + kc + u * 8;
            cp_async16(dst,         A + ga);
            cp_async16(dst + 16384, B + gb);
        }
        cp_commit();
    };

    auto load_frags = [&](uint32_t b32, int ks, Frag& f) {
#pragma unroll
        for (int mt = 0; mt < 4; mt++) {
            int r = wm * 64 + mt * 16 + (lane & 15);
            int u = 2 * ks + (lane >> 4);
            uint32_t addr = b32 + r * 128 + ((u ^ (r & 7)) << 4);
            ldm_x4(f.ah[mt][0], f.ah[mt][1], f.ah[mt][2], f.ah[mt][3], addr);
        }
#pragma unroll
        for (int np = 0; np < 2; np++) {
            int r = wn * 32 + np * 16 + (lane & 15);
            int u = 2 * ks + (lane >> 4);
            uint32_t addr = b32 + 16384 + r * 128 + ((u ^ (r & 7)) << 4);
            uint32_t t0, t1, t2, t3;
            ldm_x4(t0, t1, t2, t3, addr);
            f.bh[2 * np][0] = t0; f.bh[2 * np][1] = t2;
            f.bh[2 * np + 1][0] = t1; f.bh[2 * np + 1][1] = t3;
        }
    };

    float acc[4][4][4];
#pragma unroll
    for (int i = 0; i < 4; i++)
#pragma unroll
        for (int j = 0; j < 4; j++)
#pragma unroll
            for (int k = 0; k < 4; k++) acc[i][j][k] = 0.f;

    int NC = K >> 6;
    prefetch(0, 0);

    Frag f0, f1;
    for (int c = 0; c < NC; c++) {
        int buf = c & 1;
        if (c + 1 < NC) {
            prefetch(c + 1, buf ^ 1);
            cp_wait<1>();
        } else {
            cp_wait<0>();
        }
        __syncthreads();

        uint32_t b32 = sb + buf * 32768;
        load_frags(b32, 0, f0);
#pragma unroll
        for (int ks = 0; ks < 4; ks++) {
            Frag& cur = (ks & 1) ? f1 : f0;
            Frag& nxt = (ks & 1) ? f0 : f1;
            if (ks < 3) load_frags(b32, ks + 1, nxt);
#pragma unroll
            for (int mt = 0; mt < 4; mt++)
#pragma unroll
                for (int nt = 0; nt < 4; nt++)
                    mma_f16(acc[mt][nt], cur.ah[mt], cur.bh[nt]);
        }
        __syncthreads();
    }

    int rbase = m0 + wm * 64 + (lane >> 2);
    int cbase = n0 + wn * 32 + (lane & 3) * 2;
    bool qkv_mode = (qh != nullptr);

#pragma unroll
    for (int mt = 0; mt < 4; mt++)
#pragma unroll
        for (int nt = 0; nt < 4; nt++) {
            int row = rbase + mt * 16;
            int col = cbase + nt * 8;
            float2 v0 = make_float2(acc[mt][nt][0], acc[mt][nt][1]);
            float2 v1 = make_float2(acc[mt][nt][2], acc[mt][nt][3]);
            if (qkv_mode) {
                if (col < 2 * DINNER) {
                    int t = (col & 63) >> 1;
                    float2 cs0 = g_rope[row * 32 + t];
                    float2 cs1 = g_rope[(row + 8) * 32 + t];
                    float a = v0.x, b = v0.y;
                    v0.x = a * cs0.x - b * cs0.y;
                    v0.y = b * cs0.x + a * cs0.y;
                    a = v1.x; b = v1.y;
                    v1.x = a * cs1.x - b * cs1.y;
                    v1.y = b * cs1.x + a * cs1.y;
                }
                int sec = col >> 9;
                __nv_bfloat16 *hp, *lp;
                if (sec == 0) { hp = qh; lp = ql; }
                else if (sec == 1) { hp = kh; lp = kl; }
                else { hp = vh; lp = vl; }
                int cc = col & 511;
                split_store_bf(hp, lp, (size_t)row * DINNER + cc, v0.x, v0.y);
                split_store_bf(hp, lp, (size_t)(row + 8) * DINNER + cc, v1.x, v1.y);
            } else {
                *(float2*)(C + (size_t)row * ldc + col) = v0;
                *(float2*)(C + (size_t)(row + 8) * ldc + col) = v1;
            }
        }
}

// ---------------------------------------------------------------------------
// Tensor-core attention (R13 structure, unchanged precision path):
// 128 queries/block, 8 warps, per-warp chunk bounds + persist mini chunk.
// ---------------------------------------------------------------------------
#define AQ_H 0
#define AQ_L 16384
#define AK_H 32768
#define KV_STRIDE (272 * 128)
#define AK_L (AK_H + KV_STRIDE)
#define AV_H (AK_L + KV_STRIDE)
#define AV_L (AV_H + KV_STRIDE)
#define AP   (AV_L + KV_STRIDE)
#define ATTN_SMEM (AP + 8 * 4096)
#define NEGINF (-1e30f)

__global__ __launch_bounds__(256) void attn_kernel(
    const __nv_bfloat16* __restrict__ qh_g, const __nv_bfloat16* __restrict__ ql_g,
    const __nv_bfloat16* __restrict__ kh_g, const __nv_bfloat16* __restrict__ kl_g,
    const __nv_bfloat16* __restrict__ vh_g, const __nv_bfloat16* __restrict__ vl_g,
    __half* __restrict__ out_h) {
    extern __shared__ char smem[];
    uint32_t sb = smem_u32(smem);
    int h = blockIdx.y;
    int qs = blockIdx.x * 128;
    int tid = threadIdx.x;
    int warp = tid >> 5, lane = tid & 31;

    int kv_lo = qs - WIN; if (kv_lo < 0) kv_lo = 0;
    int cnt = qs + 128 - kv_lo;
    int P = (kv_lo > 0) ? NPERSIST : 0;
    int tot = cnt + P;

    for (int idx = tid; idx < 1024; idx += 256) {
        int r = idx >> 3, u = idx & 7;
        size_t s = (size_t)(qs + r) * DINNER + h * DH + u * 8;
        int d = r * 128 + ((u ^ (r & 7)) << 4);
        *(float4*)(smem + AQ_H + d) = *(const float4*)(qh_g + s);
        *(float4*)(smem + AQ_L + d) = *(const float4*)(ql_g + s);
    }
    float4 z = make_float4(0.f, 0.f, 0.f, 0.f);
    for (int idx = tid; idx < 2176; idx += 256) {
        int r = idx >> 3, u = idx & 7;
        int d = r * 128 + ((u ^ (r & 7)) << 4);
        if (r < tot) {
            int gk = (r < cnt) ? (kv_lo + r) : (r - cnt);
            size_t s = (size_t)gk * DINNER + h * DH + u * 8;
            *(float4*)(smem + AK_H + d) = *(const float4*)(kh_g + s);
            *(float4*)(smem + AK_L + d) = *(const float4*)(kl_g + s);
            *(float4*)(smem + AV_H + d) = *(const float4*)(vh_g + s);
            *(float4*)(smem + AV_L + d) = *(const float4*)(vl_g + s);
        } else {
            *(float4*)(smem + AK_H + d) = z;
            *(float4*)(smem + AK_L + d) = z;
            *(float4*)(smem + AV_H + d) = z;
            *(float4*)(smem + AV_L + d) = z;
        }
    }
    __syncthreads();

    uint32_t qfh[4][4], qfl[4][4];
    {
        int row = warp * 16 + (lane & 15);
#pragma unroll
        for (int ks = 0; ks < 4; ks++) {
            uint32_t a = sb + AQ_H + row * 128 + (((2 * ks + (lane >> 4)) ^ (row & 7)) << 4);
            ldm_x4(qfh[ks][0], qfh[ks][1], qfh[ks][2], qfh[ks][3], a);
            ldm_x4(qfl[ks][0], qfl[ks][1], qfl[ks][2], qfl[ks][3], a + 16384);
        }
    }

    float oacc[8][4];
#pragma unroll
    for (int i = 0; i < 8; i++)
#pragma unroll
        for (int j = 0; j < 4; j++) oacc[i][j] = 0.f;

    float m0 = NEGINF, m1 = NEGINF, l0 = 0.f, l1 = 0.f;
    int rowq0 = qs + warp * 16 + (lane >> 2);
    int rowq1 = rowq0 + 8;
    int pbase = AP + warp * 4096;

    auto process = [&](int row_base, auto NTC) {
        constexpr int NT = decltype(NTC)::value;
        constexpr int NP = NT / 2;
        float sacc[NT][4];
#pragma unroll
        for (int i = 0; i < NT; i++)
#pragma unroll
            for (int j = 0; j < 4; j++) sacc[i][j] = 0.f;

#pragma unroll
        for (int ks = 0; ks < 4; ks++) {
            uint32_t kbh[NT][2], kbl[NT][2];
#pragma unroll
            for (int np = 0; np < NP; np++) {
                int r = row_base + np * 16 + (lane & 15);
                uint32_t a = sb + AK_H + r * 128 + (((2 * ks + (lane >> 4)) ^ (r & 7)) << 4);
                uint32_t t0, t1, t2, t3;
                ldm_x4(t0, t1, t2, t3, a);
                kbh[2 * np][0] = t0; kbh[2 * np][1] = t2;
                kbh[2 * np + 1][0] = t1; kbh[2 * np + 1][1] = t3;
                ldm_x4(t0, t1, t2, t3, a + KV_STRIDE);
                kbl[2 * np][0] = t0; kbl[2 * np][1] = t2;
                kbl[2 * np + 1][0] = t1; kbl[2 * np + 1][1] = t3;
            }
#pragma unroll
            for (int nt = 0; nt < NT; nt++) {
                mma_bf16(sacc[nt], qfh[ks], kbh[nt]);
                mma_bf16(sacc[nt], qfh[ks], kbl[nt]);
                mma_bf16(sacc[nt], qfl[ks], kbh[nt]);
            }
        }

        float cm0 = NEGINF, cm1 = NEGINF;
#pragma unroll
        for (int nt = 0; nt < NT; nt++)
#pragma unroll
            for (int j = 0; j < 4; j++) {
                int key = row_base + nt * 8 + 2 * (lane & 3) + (j & 1);
                int rq = (j < 2) ? rowq0 : rowq1;
                bool ok;
                if (key >= tot) ok = false;
                else if (key < cnt) {
                    int gk = kv_lo + key;
                    ok = (gk <= rq) && ((rq - gk <= WIN) || (gk < NPERSIST));
                } else ok = true;
                float s = ok ? sacc[nt][j] * 0.125f : NEGINF;
                sacc[nt][j] = s;
                if (j < 2) cm0 = fmaxf(cm0, s); else cm1 = fmaxf(cm1, s);
            }
        cm0 = fmaxf(cm0, __shfl_xor_sync(0xffffffffu, cm0, 1));
        cm0 = fmaxf(cm0, __shfl_xor_sync(0xffffffffu, cm0, 2));
        cm1 = fmaxf(cm1, __shfl_xor_sync(0xffffffffu, cm1, 1));
        cm1 = fmaxf(cm1, __shfl_xor_sync(0xffffffffu, cm1, 2));
        float nm0 = fmaxf(m0, cm0), nm1 = fmaxf(m1, cm1);
        float c0 = __expf(m0 - nm0), c1 = __expf(m1 - nm1);
        m0 = nm0; m1 = nm1;

        __syncwarp();
        float sum0 = 0.f, sum1 = 0.f;
        int r0 = lane >> 2, r1 = r0 + 8;
        int ioff = 4 * (lane & 3);
#pragma unroll
        for (int nt = 0; nt < NT; nt++) {
            float p0 = __expf(sacc[nt][0] - m0);
            float p1 = __expf(sacc[nt][1] - m0);
            float p2 = __expf(sacc[nt][2] - m1);
            float p3 = __expf(sacc[nt][3] - m1);
            sum0 += p0 + p1;
            sum1 += p2 + p3;
            int a0 = pbase + r0 * 128 + ((nt ^ (r0 & 7)) << 4) + ioff;
            int a1 = pbase + r1 * 128 + ((nt ^ (r1 & 7)) << 4) + ioff;
            __nv_bfloat16 h0 = __float2bfloat16(p0), h1 = __float2bfloat16(p1);
            __nv_bfloat16 h2 = __float2bfloat16(p2), h3 = __float2bfloat16(p3);
            __nv_bfloat162 w;
            w.x = h0; w.y = h1; *(__nv_bfloat162*)(smem + a0) = w;
            w.x = h2; w.y = h3; *(__nv_bfloat162*)(smem + a1) = w;
            w.x = __float2bfloat16(p0 - __bfloat162float(h0));
            w.y = __float2bfloat16(p1 - __bfloat162float(h1));
            *(__nv_bfloat162*)(smem + a0 + 2048) = w;
            w.x = __float2bfloat16(p2 - __bfloat162float(h2));
            w.y = __float2bfloat16(p3 - __bfloat162float(h3));
            *(__nv_bfloat162*)(smem + a1 + 2048) = w;
        }
        sum0 += __shfl_xor_sync(0xffffffffu, sum0, 1);
        sum0 += __shfl_xor_sync(0xffffffffu, sum0, 2);
        sum1 += __shfl_xor_sync(0xffffffffu, sum1, 1);
        sum1 += __shfl_xor_sync(0xffffffffu, sum1, 2);
        l0 = l0 * c0 + sum0;
        l1 = l1 * c1 + sum1;

#pragma unroll
        for (int dt = 0; dt < 8; dt++) {
            oacc[dt][0] *= c0; oacc[dt][1] *= c0;
            oacc[dt][2] *= c1; oacc[dt][3] *= c1;
        }
        __syncwarp();

#pragma unroll
        for (int kp = 0; kp < NP; kp++) {
            uint32_t pfh[4], pfl[4];
            {
                int row = lane & 15;
                uint32_t a = sb + pbase + row * 128 + (((2 * kp + (lane >> 4)) ^ (row & 7)) << 4);
                ldm_x4(pfh[0], pfh[1], pfh[2], pfh[3], a);
                ldm_x4(pfl[0], pfl[1], pfl[2], pfl[3], a + 2048);
            }
            uint32_t vbh[8][2], vbl[8][2];
#pragma unroll
            for (int np = 0; np < 4; np++) {
                int r = row_base + kp * 16 + (lane & 7) + (((lane >> 4) & 1) << 3);
                int u = np * 2 + ((lane >> 3) & 1);
                uint32_t a = sb + AV_H + r * 128 + ((u ^ (r & 7)) << 4);
                uint32_t t0, t1, t2, t3;
                ldm_x4t(t0, t1, t2, t3, a);
                vbh[2 * np][0] = t0; vbh[2 * np][1] = t2;
                vbh[2 * np + 1][0] = t1; vbh[2 * np + 1][1] = t3;
                ldm_x4t(t0, t1, t2, t3, a + KV_STRIDE);
                vbl[2 * np][0] = t0; vbl[2 * np][1] = t2;
                vbl[2 * np + 1][0] = t1; vbl[2 * np + 1][1] = t3;
            }
#pragma unroll
            for (int dt = 0; dt < 8; dt++) {
                mma_bf16(oacc[dt], pfh, vbh[dt]);
                mma_bf16(oacc[dt], pfh, vbl[dt]);
                mma_bf16(oacc[dt], pfl, vbh[dt]);
            }
        }
        __syncwarp();
    };

    int rlo = qs + 16 * warp - WIN - kv_lo; if (rlo < 0) rlo = 0;
    int rhi = qs + 16 * warp + 15 - kv_lo;
    int ch_lo = rlo >> 6, ch_hi = rhi >> 6;
    for (int ch = ch_lo; ch <= ch_hi; ch++) process(ch * 64, IC<8>{});
    if (P > 0) process(cnt, IC<2>{});
    else if (ch_lo > 0) process(0, IC<2>{});

    float i0 = 1.0f / l0, i1 = 1.0f / l1;
#pragma unroll
    for (int dt = 0; dt < 8; dt++) {
        int col = h * DH + dt * 8 + 2 * (lane & 3);
        __half2 w;
        w.x = __float2half(oacc[dt][0] * i0);
        w.y = __float2half(oacc[dt][1] * i0);
        *(__half2*)(out_h + (size_t)rowq0 * DINNER + col) = w;
        w.x = __float2half(oacc[dt][2] * i1);
        w.y = __float2half(oacc[dt][3] * i1);
        *(__half2*)(out_h + (size_t)rowq1 * DINNER + col) = w;
    }
}

// ---------------------------------------------------------------------------
extern "C" void kernel_launch(void* const* d_in, const int* in_sizes, int n_in,
                              void* d_out, int out_size) {
    const float* seq   = (const float*)d_in[0];
    const float* g     = (const float*)d_in[1];
    const float* w_qkv = (const float*)d_in[2];
    const float* w_out = (const float*)d_in[3];
    float* out = (float*)d_out;

    __half *ah, *wqh, *woh, *ath;
    __nv_bfloat16 *qh, *ql, *kh, *kl, *vh, *vl;
    cudaGetSymbolAddress((void**)&ah, g_a_h);
    cudaGetSymbolAddress((void**)&wqh, g_wqkvT_h);
    cudaGetSymbolAddress((void**)&woh, g_woutT_h);
    cudaGetSymbolAddress((void**)&ath, g_attn_h);
    cudaGetSymbolAddress((void**)&qh, g_q_hi);
    cudaGetSymbolAddress((void**)&ql, g_q_lo);
    cudaGetSymbolAddress((void**)&kh, g_k_hi);
    cudaGetSymbolAddress((void**)&kl, g_k_lo);
    cudaGetSymbolAddress((void**)&vh, g_v_hi);
    cudaGetSymbolAddress((void**)&vl, g_v_lo);

    cudaFuncSetAttribute(attn_kernel, cudaFuncAttributeMaxDynamicSharedMemorySize,
                         ATTN_SMEM);
    cudaFuncSetAttribute(gemm_f16_kernel, cudaFuncAttributeMaxDynamicSharedMemorySize,
                         GEMM_SMEM);

    rope_table_kernel<<<(N_SEQ * 32 + 255) / 256, 256>>>();
    rmsnorm_cvt_kernel<<<N_SEQ, 256>>>(seq, g, ah);
    transpose_cvt_kernel<<<dim3(QKVC / 32, DMODEL / 32), dim3(32, 8)>>>(
        w_qkv, DMODEL, QKVC, wqh);
    transpose_cvt_kernel<<<dim3(DMODEL / 32, DINNER / 32), dim3(32, 8)>>>(
        w_out, DINNER, DMODEL, woh);

    gemm_f16_kernel<<<dim3(QKVC / 128, N_SEQ / 128), 256, GEMM_SMEM>>>(
        ah, wqh, nullptr, DMODEL, QKVC, qh, ql, kh, kl, vh, vl);

    attn_kernel<<<dim3(N_SEQ / 128, HEADS), 256, ATTN_SMEM>>>(
        qh, ql, kh, kl, vh, vl, ath);

    gemm_f16_kernel<<<dim3(DMODEL / 128, N_SEQ / 128), 256, GEMM_SMEM>>>(
        ath, woh, out, DINNER, DMODEL,
        nullptr, nullptr, nullptr, nullptr, nullptr, nullptr);
}

// round 17
// speedup vs baseline: 2.8656x; 1.2498x over previous
#include <cuda_runtime.h>
#include <cuda_bf16.h>
#include <cuda_fp16.h>
#include <math.h>
#include <stdint.h>

#define N_SEQ   4096
#define DMODEL  1024
#define HEADS   8
#define DH      64
#define DINNER  512
#define QKVC    1536
#define WIN     128
#define NPERSIST 4

// ---------------- scratch (device globals; allocation-free rule) ------------
__device__ float2 g_rope[N_SEQ * 32];
__device__ __half g_a_h[N_SEQ * DMODEL];
__device__ __half g_wqkvT_h[QKVC * DMODEL];
__device__ __half g_woutT_h[DMODEL * DINNER];
__device__ __half g_q_h[N_SEQ * DINNER];
__device__ __half g_k_h[N_SEQ * DINNER];
__device__ __half g_v_h[N_SEQ * DINNER];
__device__ __half g_attn_h[N_SEQ * DINNER];

template <int N> struct IC { static constexpr int value = N; };

// ---------------- helpers ----------------------------------------------
__device__ __forceinline__ uint32_t smem_u32(const void* p) {
    uint32_t a;
    asm("{ .reg .u64 t; cvta.to.shared.u64 t, %1; cvt.u32.u64 %0, t; }" : "=r"(a) : "l"(p));
    return a;
}
__device__ __forceinline__ void cp_async16(uint32_t dst, const void* src) {
    asm volatile("cp.async.cg.shared.global [%0], [%1], 16;" :: "r"(dst), "l"(src));
}
__device__ __forceinline__ void cp_commit() {
    asm volatile("cp.async.commit_group;" ::: "memory");
}
template <int N>
__device__ __forceinline__ void cp_wait() {
    asm volatile("cp.async.wait_group %0;" :: "n"(N) : "memory");
}
__device__ __forceinline__ void ldm_x4(uint32_t& r0, uint32_t& r1, uint32_t& r2,
                                       uint32_t& r3, uint32_t addr) {
    asm volatile("ldmatrix.sync.aligned.m8n8.x4.shared.b16 {%0,%1,%2,%3}, [%4];"
                 : "=r"(r0), "=r"(r1), "=r"(r2), "=r"(r3) : "r"(addr));
}
__device__ __forceinline__ void ldm_x4t(uint32_t& r0, uint32_t& r1, uint32_t& r2,
                                        uint32_t& r3, uint32_t addr) {
    asm volatile("ldmatrix.sync.aligned.m8n8.x4.trans.shared.b16 {%0,%1,%2,%3}, [%4];"
                 : "=r"(r0), "=r"(r1), "=r"(r2), "=r"(r3) : "r"(addr));
}
__device__ __forceinline__ void mma_f16(float* d, const uint32_t* a, const uint32_t* b) {
    asm volatile("mma.sync.aligned.m16n8k16.row.col.f32.f16.f16.f32 "
                 "{%0,%1,%2,%3}, {%4,%5,%6,%7}, {%8,%9}, {%0,%1,%2,%3};"
                 : "+f"(d[0]), "+f"(d[1]), "+f"(d[2]), "+f"(d[3])
                 : "r"(a[0]), "r"(a[1]), "r"(a[2]), "r"(a[3]), "r"(b[0]), "r"(b[1]));
}

// ---------------------------------------------------------------------------
// RoPE table
// ---------------------------------------------------------------------------
__global__ void rope_table_kernel() {
    int idx = blockIdx.x * blockDim.x + threadIdx.x;
    if (idx >= N_SEQ * 32) return;
    int n = idx >> 5;
    int t = idx & 31;
    float inv = (float)exp(-(double)t * (9.210340371976184 / 32.0));
    float s, c;
    sincosf((float)n * inv, &s, &c);
    g_rope[idx] = make_float2(c, s);
}

// ---------------------------------------------------------------------------
// RMSNorm -> fp16 (single plane)
// ---------------------------------------------------------------------------
__global__ void rmsnorm_cvt_kernel(const float* __restrict__ seq,
                                   const float* __restrict__ g,
                                   __half* __restrict__ out) {
    int row = blockIdx.x;
    int t = threadIdx.x;
    float4 v = ((const float4*)(seq + row * DMODEL))[t];
    float ss = v.x * v.x + v.y * v.y + v.z * v.z + v.w * v.w;
#pragma unroll
    for (int o = 16; o > 0; o >>= 1) ss += __shfl_xor_sync(0xffffffffu, ss, o);
    __shared__ float ws[8];
    if ((t & 31) == 0) ws[t >> 5] = ss;
    __syncthreads();
    float tot = ws[0] + ws[1] + ws[2] + ws[3] + ws[4] + ws[5] + ws[6] + ws[7];
    float inv = rsqrtf(tot * (1.0f / (float)DMODEL) + 1.1920929e-07f);
    float4 gv = ((const float4*)g)[t];
    size_t base = (size_t)row * DMODEL + t * 4;
    __half2 w;
    w.x = __float2half(v.x * inv * gv.x);
    w.y = __float2half(v.y * inv * gv.y);
    *(__half2*)(out + base) = w;
    w.x = __float2half(v.z * inv * gv.z);
    w.y = __float2half(v.w * inv * gv.w);
    *(__half2*)(out + base + 2) = w;
}

// ---------------------------------------------------------------------------
// Transpose + fp16 convert: src[K][N] -> dst[N][K] (single plane)
// ---------------------------------------------------------------------------
__global__ void transpose_cvt_kernel(const float* __restrict__ src, int K, int N,
                                     __half* __restrict__ dst) {
    __shared__ float tile[32][33];
    int bx = blockIdx.x, by = blockIdx.y;
    int tx = threadIdx.x, ty = threadIdx.y;
#pragma unroll
    for (int i = 0; i < 4; i++) {
        int k = by * 32 + ty + 8 * i;
        int n = bx * 32 + tx;
        tile[ty + 8 * i][tx] = src[(size_t)k * N + n];
    }
    __syncthreads();
#pragma unroll
    for (int i = 0; i < 4; i++) {
        int n = bx * 32 + ty + 8 * i;
        int k = by * 32 + tx;
        dst[(size_t)n * K + k] = __float2half(tile[tx][ty + 8 * i]);
    }
}

// ---------------------------------------------------------------------------
// Single-plane fp16 GEMM via mma.sync: C = A * B^T.
// qkv mode (qh != nullptr): fused table RoPE + fp16 q/k/v planes.
// ---------------------------------------------------------------------------
#define GEMM_SMEM (2 * 2 * 16384)

struct Frag {
    uint32_t ah[4][4], bh[4][2];
};

__global__ __launch_bounds__(256)
void gemm_f16_kernel(const __half* __restrict__ A,
                     const __half* __restrict__ B,
                     float* __restrict__ C, int K, int ldc,
                     __half* qh, __half* kh, __half* vh) {
    extern __shared__ char smem[];
    uint32_t sb = smem_u32(smem);
    int tid = threadIdx.x;
    int wid = tid >> 5, lane = tid & 31;
    int m0 = blockIdx.y * 128, n0 = blockIdx.x * 128;
    int wm = wid & 1;
    int wn = wid >> 1;

    auto prefetch = [&](int c, int buf) {
        int kc = c << 6;
        uint32_t b32 = sb + buf * 32768;
#pragma unroll
        for (int i = 0; i < 4; i++) {
            int idx = tid + 256 * i;
            int r = idx >> 3, u = idx & 7;
            uint32_t dst = b32 + r * 128 + ((u ^ (r & 7)) << 4);
            size_t ga = (size_t)(m0 + r) * K + kc + u * 8;
            size_t gb = (size_t)(n0 + r) * K + kc + u * 8;
            cp_async16(dst,         A + ga);
            cp_async16(dst + 16384, B + gb);
        }
        cp_commit();
    };

    auto load_frags = [&](uint32_t b32, int ks, Frag& f) {
#pragma unroll
        for (int mt = 0; mt < 4; mt++) {
            int r = wm * 64 + mt * 16 + (lane & 15);
            int u = 2 * ks + (lane >> 4);
            uint32_t addr = b32 + r * 128 + ((u ^ (r & 7)) << 4);
            ldm_x4(f.ah[mt][0], f.ah[mt][1], f.ah[mt][2], f.ah[mt][3], addr);
        }
#pragma unroll
        for (int np = 0; np < 2; np++) {
            int r = wn * 32 + np * 16 + (lane & 15);
            int u = 2 * ks + (lane >> 4);
            uint32_t addr = b32 + 16384 + r * 128 + ((u ^ (r & 7)) << 4);
            uint32_t t0, t1, t2, t3;
            ldm_x4(t0, t1, t2, t3, addr);
            f.bh[2 * np][0] = t0; f.bh[2 * np][1] = t2;
            f.bh[2 * np + 1][0] = t1; f.bh[2 * np + 1][1] = t3;
        }
    };

    float acc[4][4][4];
#pragma unroll
    for (int i = 0; i < 4; i++)
#pragma unroll
        for (int j = 0; j < 4; j++)
#pragma unroll
            for (int k = 0; k < 4; k++) acc[i][j][k] = 0.f;

    int NC = K >> 6;
    prefetch(0, 0);

    Frag f0, f1;
    for (int c = 0; c < NC; c++) {
        int buf = c & 1;
        if (c + 1 < NC) {
            prefetch(c + 1, buf ^ 1);
            cp_wait<1>();
        } else {
            cp_wait<0>();
        }
        __syncthreads();

        uint32_t b32 = sb + buf * 32768;
        load_frags(b32, 0, f0);
#pragma unroll
        for (int ks = 0; ks < 4; ks++) {
            Frag& cur = (ks & 1) ? f1 : f0;
            Frag& nxt = (ks & 1) ? f0 : f1;
            if (ks < 3) load_frags(b32, ks + 1, nxt);
#pragma unroll
            for (int mt = 0; mt < 4; mt++)
#pragma unroll
                for (int nt = 0; nt < 4; nt++)
                    mma_f16(acc[mt][nt], cur.ah[mt], cur.bh[nt]);
        }
        __syncthreads();
    }

    int rbase = m0 + wm * 64 + (lane >> 2);
    int cbase = n0 + wn * 32 + (lane & 3) * 2;
    bool qkv_mode = (qh != nullptr);

#pragma unroll
    for (int mt = 0; mt < 4; mt++)
#pragma unroll
        for (int nt = 0; nt < 4; nt++) {
            int row = rbase + mt * 16;
            int col = cbase + nt * 8;
            float2 v0 = make_float2(acc[mt][nt][0], acc[mt][nt][1]);
            float2 v1 = make_float2(acc[mt][nt][2], acc[mt][nt][3]);
            if (qkv_mode) {
                if (col < 2 * DINNER) {
                    int t = (col & 63) >> 1;
                    float2 cs0 = g_rope[row * 32 + t];
                    float2 cs1 = g_rope[(row + 8) * 32 + t];
                    float a = v0.x, b = v0.y;
                    v0.x = a * cs0.x - b * cs0.y;
                    v0.y = b * cs0.x + a * cs0.y;
                    a = v1.x; b = v1.y;
                    v1.x = a * cs1.x - b * cs1.y;
                    v1.y = b * cs1.x + a * cs1.y;
                }
                int sec = col >> 9;
                __half* hp = (sec == 0) ? qh : (sec == 1) ? kh : vh;
                int cc = col & 511;
                __half2 w;
                w.x = __float2half(v0.x); w.y = __float2half(v0.y);
                *(__half2*)(hp + (size_t)row * DINNER + cc) = w;
                w.x = __float2half(v1.x); w.y = __float2half(v1.y);
                *(__half2*)(hp + (size_t)(row + 8) * DINNER + cc) = w;
            } else {
                *(float2*)(C + (size_t)row * ldc + col) = v0;
                *(float2*)(C + (size_t)(row + 8) * ldc + col) = v1;
            }
        }
}

// ---------------------------------------------------------------------------
// Tensor-core attention v3: single-plane fp16 Q/K/V/P. 128 queries/block,
// 8 warps, per-warp chunk bounds + persist mini chunk. SMEM 100KB -> 2 CTAs/SM.
// ---------------------------------------------------------------------------
#define AQ 0
#define AK 16384
#define KV_STRIDE (272 * 128)
#define AV (AK + KV_STRIDE)
#define AP (AV + KV_STRIDE)
#define ATTN_SMEM (AP + 8 * 2048)
#define NEGINF (-1e30f)

__global__ __launch_bounds__(256) void attn_kernel(
    const __half* __restrict__ qh_g, const __half* __restrict__ kh_g,
    const __half* __restrict__ vh_g, __half* __restrict__ out_h) {
    extern __shared__ char smem[];
    uint32_t sb = smem_u32(smem);
    int h = blockIdx.y;
    int qs = blockIdx.x * 128;
    int tid = threadIdx.x;
    int warp = tid >> 5, lane = tid & 31;

    int kv_lo = qs - WIN; if (kv_lo < 0) kv_lo = 0;
    int cnt = qs + 128 - kv_lo;
    int P = (kv_lo > 0) ? NPERSIST : 0;
    int tot = cnt + P;

    for (int idx = tid; idx < 1024; idx += 256) {
        int r = idx >> 3, u = idx & 7;
        size_t s = (size_t)(qs + r) * DINNER + h * DH + u * 8;
        int d = r * 128 + ((u ^ (r & 7)) << 4);
        *(float4*)(smem + AQ + d) = *(const float4*)(qh_g + s);
    }
    float4 z = make_float4(0.f, 0.f, 0.f, 0.f);
    for (int idx = tid; idx < 2176; idx += 256) {
        int r = idx >> 3, u = idx & 7;
        int d = r * 128 + ((u ^ (r & 7)) << 4);
        if (r < tot) {
            int gk = (r < cnt) ? (kv_lo + r) : (r - cnt);
            size_t s = (size_t)gk * DINNER + h * DH + u * 8;
            *(float4*)(smem + AK + d) = *(const float4*)(kh_g + s);
            *(float4*)(smem + AV + d) = *(const float4*)(vh_g + s);
        } else {
            *(float4*)(smem + AK + d) = z;
            *(float4*)(smem + AV + d) = z;
        }
    }
    __syncthreads();

    uint32_t qf[4][4];
    {
        int row = warp * 16 + (lane & 15);
#pragma unroll
        for (int ks = 0; ks < 4; ks++) {
            uint32_t a = sb + AQ + row * 128 + (((2 * ks + (lane >> 4)) ^ (row & 7)) << 4);
            ldm_x4(qf[ks][0], qf[ks][1], qf[ks][2], qf[ks][3], a);
        }
    }

    float oacc[8][4];
#pragma unroll
    for (int i = 0; i < 8; i++)
#pragma unroll
        for (int j = 0; j < 4; j++) oacc[i][j] = 0.f;

    float m0 = NEGINF, m1 = NEGINF, l0 = 0.f, l1 = 0.f;
    int rowq0 = qs + warp * 16 + (lane >> 2);
    int rowq1 = rowq0 + 8;
    int pbase = AP + warp * 2048;

    auto process = [&](int row_base, auto NTC) {
        constexpr int NT = decltype(NTC)::value;
        constexpr int NP = NT / 2;
        float sacc[NT][4];
#pragma unroll
        for (int i = 0; i < NT; i++)
#pragma unroll
            for (int j = 0; j < 4; j++) sacc[i][j] = 0.f;

#pragma unroll
        for (int ks = 0; ks < 4; ks++) {
            uint32_t kb[NT][2];
#pragma unroll
            for (int np = 0; np < NP; np++) {
                int r = row_base + np * 16 + (lane & 15);
                uint32_t a = sb + AK + r * 128 + (((2 * ks + (lane >> 4)) ^ (r & 7)) << 4);
                uint32_t t0, t1, t2, t3;
                ldm_x4(t0, t1, t2, t3, a);
                kb[2 * np][0] = t0; kb[2 * np][1] = t2;
                kb[2 * np + 1][0] = t1; kb[2 * np + 1][1] = t3;
            }
#pragma unroll
            for (int nt = 0; nt < NT; nt++)
                mma_f16(sacc[nt], qf[ks], kb[nt]);
        }

        float cm0 = NEGINF, cm1 = NEGINF;
#pragma unroll
        for (int nt = 0; nt < NT; nt++)
#pragma unroll
            for (int j = 0; j < 4; j++) {
                int key = row_base + nt * 8 + 2 * (lane & 3) + (j & 1);
                int rq = (j < 2) ? rowq0 : rowq1;
                bool ok;
                if (key >= tot) ok = false;
                else if (key < cnt) {
                    int gk = kv_lo + key;
                    ok = (gk <= rq) && ((rq - gk <= WIN) || (gk < NPERSIST));
                } else ok = true;
                float s = ok ? sacc[nt][j] * 0.125f : NEGINF;
                sacc[nt][j] = s;
                if (j < 2) cm0 = fmaxf(cm0, s); else cm1 = fmaxf(cm1, s);
            }
        cm0 = fmaxf(cm0, __shfl_xor_sync(0xffffffffu, cm0, 1));
        cm0 = fmaxf(cm0, __shfl_xor_sync(0xffffffffu, cm0, 2));
        cm1 = fmaxf(cm1, __shfl_xor_sync(0xffffffffu, cm1, 1));
        cm1 = fmaxf(cm1, __shfl_xor_sync(0xffffffffu, cm1, 2));
        float nm0 = fmaxf(m0, cm0), nm1 = fmaxf(m1, cm1);
        float c0 = __expf(m0 - nm0), c1 = __expf(m1 - nm1);
        m0 = nm0; m1 = nm1;

        __syncwarp();
        float sum0 = 0.f, sum1 = 0.f;
        int r0 = lane >> 2, r1 = r0 + 8;
        int ioff = 4 * (lane & 3);
#pragma unroll
        for (int nt = 0; nt < NT; nt++) {
            float p0 = __expf(sacc[nt][0] - m0);
            float p1 = __expf(sacc[nt][1] - m0);
            float p2 = __expf(sacc[nt][2] - m1);
            float p3 = __expf(sacc[nt][3] - m1);
            sum0 += p0 + p1;
            sum1 += p2 + p3;
            int a0 = pbase + r0 * 128 + ((nt ^ (r0 & 7)) << 4) + ioff;
            int a1 = pbase + r1 * 128 + ((nt ^ (r1 & 7)) << 4) + ioff;
            __half2 w;
            w.x = __float2half(p0); w.y = __float2half(p1);
            *(__half2*)(smem + a0) = w;
            w.x = __float2half(p2); w.y = __float2half(p3);
            *(__half2*)(smem + a1) = w;
        }
        sum0 += __shfl_xor_sync(0xffffffffu, sum0, 1);
        sum0 += __shfl_xor_sync(0xffffffffu, sum0, 2);
        sum1 += __shfl_xor_sync(0xffffffffu, sum1, 1);
        sum1 += __shfl_xor_sync(0xffffffffu, sum1, 2);
        l0 = l0 * c0 + sum0;
        l1 = l1 * c1 + sum1;

#pragma unroll
        for (int dt = 0; dt < 8; dt++) {
            oacc[dt][0] *= c0; oacc[dt][1] *= c0;
            oacc[dt][2] *= c1; oacc[dt][3] *= c1;
        }
        __syncwarp();

#pragma unroll
        for (int kp = 0; kp < NP; kp++) {
            uint32_t pf[4];
            {
                int row = lane & 15;
                uint32_t a = sb + pbase + row * 128 + (((2 * kp + (lane >> 4)) ^ (row & 7)) << 4);
                ldm_x4(pf[0], pf[1], pf[2], pf[3], a);
            }
            uint32_t vb[8][2];
#pragma unroll
            for (int np = 0; np < 4; np++) {
                int r = row_base + kp * 16 + (lane & 7) + (((lane >> 4) & 1) << 3);
                int u = np * 2 + ((lane >> 3) & 1);
                uint32_t a = sb + AV + r * 128 + ((u ^ (r & 7)) << 4);
                uint32_t t0, t1, t2, t3;
                ldm_x4t(t0, t1, t2, t3, a);
                vb[2 * np][0] = t0; vb[2 * np][1] = t2;
                vb[2 * np + 1][0] = t1; vb[2 * np + 1][1] = t3;
            }
#pragma unroll
            for (int dt = 0; dt < 8; dt++)
                mma_f16(oacc[dt], pf, vb[dt]);
        }
        __syncwarp();
    };

    int rlo = qs + 16 * warp - WIN - kv_lo; if (rlo < 0) rlo = 0;
    int rhi = qs + 16 * warp + 15 - kv_lo;
    int ch_lo = rlo >> 6, ch_hi = rhi >> 6;
    for (int ch = ch_lo; ch <= ch_hi; ch++) process(ch * 64, IC<8>{});
    if (P > 0) process(cnt, IC<2>{});
    else if (ch_lo > 0) process(0, IC<2>{});

    float i0 = 1.0f / l0, i1 = 1.0f / l1;
#pragma unroll
    for (int dt = 0; dt < 8; dt++) {
        int col = h * DH + dt * 8 + 2 * (lane & 3);
        __half2 w;
        w.x = __float2half(oacc[dt][0] * i0);
        w.y = __float2half(oacc[dt][1] * i0);
        *(__half2*)(out_h + (size_t)rowq0 * DINNER + col) = w;
        w.x = __float2half(oacc[dt][2] * i1);
        w.y = __float2half(oacc[dt][3] * i1);
        *(__half2*)(out_h + (size_t)rowq1 * DINNER + col) = w;
    }
}

// ---------------------------------------------------------------------------
extern "C" void kernel_launch(void* const* d_in, const int* in_sizes, int n_in,
                              void* d_out, int out_size) {
    const float* seq   = (const float*)d_in[0];
    const float* g     = (const float*)d_in[1];
    const float* w_qkv = (const float*)d_in[2];
    const float* w_out = (const float*)d_in[3];
    float* out = (float*)d_out;

    __half *ah, *wqh, *woh, *ath, *qh, *kh, *vh;
    cudaGetSymbolAddress((void**)&ah, g_a_h);
    cudaGetSymbolAddress((void**)&wqh, g_wqkvT_h);
    cudaGetSymbolAddress((void**)&woh, g_woutT_h);
    cudaGetSymbolAddress((void**)&ath, g_attn_h);
    cudaGetSymbolAddress((void**)&qh, g_q_h);
    cudaGetSymbolAddress((void**)&kh, g_k_h);
    cudaGetSymbolAddress((void**)&vh, g_v_h);

    cudaFuncSetAttribute(attn_kernel, cudaFuncAttributeMaxDynamicSharedMemorySize,
                         ATTN_SMEM);
    cudaFuncSetAttribute(gemm_f16_kernel, cudaFuncAttributeMaxDynamicSharedMemorySize,
                         GEMM_SMEM);

    rope_table_kernel<<<(N_SEQ * 32 + 255) / 256, 256>>>();
    rmsnorm_cvt_kernel<<<N_SEQ, 256>>>(seq, g, ah);
    transpose_cvt_kernel<<<dim3(QKVC / 32, DMODEL / 32), dim3(32, 8)>>>(
        w_qkv, DMODEL, QKVC, wqh);
    transpose_cvt_kernel<<<dim3(DMODEL / 32, DINNER / 32), dim3(32, 8)>>>(
        w_out, DINNER, DMODEL, woh);

    gemm_f16_kernel<<<dim3(QKVC / 128, N_SEQ / 128), 256, GEMM_SMEM>>>(
        ah, wqh, nullptr, DMODEL, QKVC, qh, kh, vh);

    attn_kernel<<<dim3(N_SEQ / 128, HEADS), 256, ATTN_SMEM>>>(qh, kh, vh, ath);

    gemm_f16_kernel<<<dim3(DMODEL / 128, N_SEQ / 128), 256, GEMM_SMEM>>>(
        ath, woh, out, DINNER, DMODEL, nullptr, nullptr, nullptr);
}